// round 6
// baseline (speedup 1.0000x reference)
#include <cuda_runtime.h>

#define B_    16
#define N_    2048
#define D_    1024
#define KH    15
#define KL    5
#define ROWS  320      // B_*KH + B_*KL
#define HROWS 240      // B_*KH
#define SPLITK 4
#define KC    (D_ / SPLITK)   // 256

#define BM 64
#define BN 64
#define BK 16

// ---------------- scratch (no allocations allowed) ----------------
__device__ unsigned int g_pmax[B_];
__device__ unsigned int g_pmin[B_];
__device__ float        g_psum[B_];
__device__ int          g_idx[ROWS];
__device__ int          g_val[ROWS];
__device__ int          g_lab[ROWS];
__device__ __align__(16) float g_Gk[SPLITK][ROWS * ROWS];
__device__ float        g_per[ROWS];
__device__ int          g_bar1;   // 32-block barrier in k_selall
__device__ int          g_fin1;   // reset helper
__device__ int          g_cnt3;   // completion counter in k_loss

// ---------------- helpers ----------------
__device__ __forceinline__ unsigned long long u64min(unsigned long long a,
                                                     unsigned long long b) {
    return a < b ? a : b;
}

// butterfly min-reduce: every lane ends with the warp minimum
__device__ __forceinline__ unsigned long long warpmin(unsigned long long v) {
#pragma unroll
    for (int o = 16; o; o >>= 1)
        v = u64min(v, __shfl_xor_sync(0xffffffffu, v, o));
    return v;
}

__device__ __forceinline__ unsigned long long f32x2_fma(unsigned long long c,
                                                        unsigned long long a,
                                                        unsigned long long b) {
    asm("fma.rn.f32x2 %0, %1, %2, %0;" : "+l"(c) : "l"(a), "l"(b));
    return c;
}

__device__ __forceinline__ unsigned long long dup_f32(float x) {
    unsigned long long r;
    unsigned u = __float_as_uint(x);
    asm("mov.b64 %0, {%1, %1};" : "=l"(r) : "r"(u));
    return r;
}

__device__ __forceinline__ int ld_cg(const int* p) {
    int v;
    asm volatile("ld.global.cg.b32 %0, [%1];" : "=r"(v) : "l"(p));
    return v;
}

// ================= K1: bag partials + selection (32 blocks) =================
// blocks 0-15: HIGH top-15 of bag bid; blocks 16-31: LOW picks of bag bid-16.
// key = (score_bits << 32) | idx -> lexicographic (score, idx), matching
// jnp stable ascending argsort (score >= 0). Only the selected SET (and the
// even ranks for LOW) matters: order within a bag is loss-invariant.
__global__ void __launch_bounds__(256) k_selall(const float* __restrict__ score,
                                                const int* __restrict__ label) {
    __shared__ unsigned long long s_cand[128];
    __shared__ unsigned s_mx[8], s_mn[8];
    __shared__ float s_sm[8];
    int bid = blockIdx.x, tid = threadIdx.x;
    int lane = tid & 31, warp = tid >> 5;
    bool isHigh = bid < B_;
    int b = isHigh ? bid : bid - B_;

    float sc[8];
#pragma unroll
    for (int i = 0; i < 8; i++) sc[i] = score[b * N_ + tid + i * 256];
    if (tid < 128) s_cand[tid] = ~0ULL;

    // ---- bag partials (HIGH blocks only, one per bag) ----
    if (isHigh) {
        unsigned mx = 0u, mn = 0xFFFFFFFFu;
        float s = 0.f;
#pragma unroll
        for (int i = 0; i < 8; i++) {
            unsigned bb = __float_as_uint(sc[i]);   // score >= 0 -> monotonic
            mx = max(mx, bb);
            mn = min(mn, bb);
            s += sc[i];
        }
#pragma unroll
        for (int o = 16; o; o >>= 1) {
            mx = max(mx, __shfl_down_sync(0xffffffffu, mx, o));
            mn = min(mn, __shfl_down_sync(0xffffffffu, mn, o));
            s += __shfl_down_sync(0xffffffffu, s, o);
        }
        if (lane == 0) { s_mx[warp] = mx; s_mn[warp] = mn; s_sm[warp] = s; }
        __syncthreads();
        if (tid == 0) {
            for (int w = 1; w < 8; w++) {
                mx = max(mx, s_mx[w]); mn = min(mn, s_mn[w]); s += s_sm[w];
            }
            g_pmax[b] = mx; g_pmin[b] = mn; g_psum[b] = s;
        }
    }

    // ---- grid sync over 32 blocks ----
    __syncthreads();
    if (tid == 0) {
        __threadfence();
        atomicAdd(&g_bar1, 1);
        while (ld_cg(&g_bar1) < 32) { }
        __threadfence();
    }
    __syncthreads();

    // ---- global bounds ----
    unsigned mxb = 0u, mnb = 0xFFFFFFFFu;
#pragma unroll
    for (int i = 0; i < B_; i++) {
        mxb = max(mxb, g_pmax[i]);
        mnb = min(mnb, g_pmin[i]);
    }
    float lo, hi;
    if (isHigh) { hi = __uint_as_float(mxb); lo = hi - 0.3f; }
    else        { lo = __uint_as_float(mnb); hi = lo + 1e-9f; }

    unsigned long long key[8];
#pragma unroll
    for (int i = 0; i < 8; i++) {
        key[i] = (sc[i] >= lo && sc[i] <= hi)
            ? (((unsigned long long)__float_as_uint(sc[i]) << 32) |
               (unsigned)(tid + i * 256))
            : ~0ULL;
    }

    int nl = isHigh ? KH : 10;      // rounds (local and merge)

    // ---- phase 1: each warp extracts its local top-nl (shuffle only) ----
    {
        unsigned long long loc = key[0];
#pragma unroll
        for (int i = 1; i < 8; i++) loc = u64min(loc, key[i]);
        for (int t = 0; t < nl; t++) {
            unsigned long long m = warpmin(loc);
            if (m == ~0ULL) break;                    // warp exhausted
            if (lane == 0) s_cand[warp * nl + t] = m;
            if (loc == m) {                           // unique owner pops
#pragma unroll
                for (int i = 0; i < 8; i++) if (key[i] == m) key[i] = ~0ULL;
                loc = key[0];
#pragma unroll
                for (int i = 1; i < 8; i++) loc = u64min(loc, key[i]);
            }
        }
    }
    __syncthreads();

    // ---- phase 2: warp 0 merges the 8*nl candidates ----
    if (warp == 0) {
        unsigned long long cand[4];
#pragma unroll
        for (int j = 0; j < 4; j++) cand[j] = s_cand[lane + 32 * j];
        unsigned long long loc = u64min(u64min(cand[0], cand[1]),
                                        u64min(cand[2], cand[3]));
        int labb = isHigh ? label[b] : 2;
        unsigned long long myv = ~0ULL;               // lane t's winner
        int tend = nl;
        for (int t = 0; t < nl; t++) {
            unsigned long long m = warpmin(loc);
            if (m == ~0ULL) { tend = t; break; }
            if (lane == t) myv = m;
            if (loc == m) {
#pragma unroll
                for (int j = 0; j < 4; j++) if (cand[j] == m) cand[j] = ~0ULL;
                loc = u64min(u64min(cand[0], cand[1]),
                             u64min(cand[2], cand[3]));
            }
        }
        if (isHigh) {
            if (lane < KH) {
                int r = b * KH + lane;
                if (lane < tend) {
                    g_val[r] = 1;
                    g_idx[r] = b * N_ + (int)(myv & 0xFFFFFFFFULL);
                } else { g_val[r] = 0; g_idx[r] = 0; }
                g_lab[r] = labb;
            }
        } else {
            // keep even ranks 0,2,4,6,8 -> slot j gets rank 2j
            unsigned long long ev = __shfl_sync(0xffffffffu, myv,
                                                (lane < KL) ? 2 * lane : 0);
            if (lane < KL) {
                int r = HROWS + b * KL + lane;
                if (2 * lane < tend) {
                    g_val[r] = 1;
                    g_idx[r] = b * N_ + (int)(ev & 0xFFFFFFFFULL);
                } else { g_val[r] = 0; g_idx[r] = 0; }
                g_lab[r] = 2;  // N_CLASSES
            }
        }
    }

    // ---- reset barrier state for next graph replay ----
    if (tid == 0) {
        int o = atomicAdd(&g_fin1, 1);
        if (o == 31) { g_bar1 = 0; g_fin1 = 0; __threadfence(); }
    }
}

// ===== K2: gram G = X X^T (320x320, K=1024), fused gather, double-buffered ===
__global__ void __launch_bounds__(256) k_gemm(const float* __restrict__ fea) {
    __shared__ __align__(16) float As[2][BK][BM + 2];
    __shared__ __align__(16) float Bs[2][BK][BN + 2];
    int kz = blockIdx.x & (SPLITK - 1), tile = blockIdx.x / SPLITK;
    int bm = tile / 5, bn = tile % 5;
    int tid = threadIdx.x;
    int tx = tid & 15, ty = tid >> 4;
    int tx4 = tx * 4, ty4 = ty * 4;

    unsigned long long cc[4][2];
#pragma unroll
    for (int i = 0; i < 4; i++) { cc[i][0] = 0ULL; cc[i][1] = 0ULL; }

    int loadRow = tid >> 2;           // 0..63
    int loadK4  = (tid & 3) * 4;      // 0,4,8,12
    // indirect gather: invalid rows point at row 0; masked in k_loss
    const float* A0 = fea + (size_t)g_idx[bm * BM + loadRow] * D_ + kz * KC + loadK4;
    const float* B0 = fea + (size_t)g_idx[bn * BN + loadRow] * D_ + kz * KC + loadK4;

    float4 a = *(const float4*)A0;
    float4 b4 = *(const float4*)B0;
    As[0][loadK4 + 0][loadRow] = a.x;
    As[0][loadK4 + 1][loadRow] = a.y;
    As[0][loadK4 + 2][loadRow] = a.z;
    As[0][loadK4 + 3][loadRow] = a.w;
    Bs[0][loadK4 + 0][loadRow] = b4.x;
    Bs[0][loadK4 + 1][loadRow] = b4.y;
    Bs[0][loadK4 + 2][loadRow] = b4.z;
    Bs[0][loadK4 + 3][loadRow] = b4.w;
    __syncthreads();

#pragma unroll
    for (int it = 0; it < KC / BK; it++) {
        int cur = it & 1;
        if (it < KC / BK - 1) {                      // prefetch next slab
            a  = *(const float4*)(A0 + (it + 1) * BK);
            b4 = *(const float4*)(B0 + (it + 1) * BK);
        }
#pragma unroll
        for (int k = 0; k < BK; k++) {
            float2 a01 = *(const float2*)&As[cur][k][ty4];
            float2 a23 = *(const float2*)&As[cur][k][ty4 + 2];
            unsigned long long bp0 = *(const unsigned long long*)&Bs[cur][k][tx4];
            unsigned long long bp1 = *(const unsigned long long*)&Bs[cur][k][tx4 + 2];
            unsigned long long A0d = dup_f32(a01.x);
            unsigned long long A1d = dup_f32(a01.y);
            unsigned long long A2d = dup_f32(a23.x);
            unsigned long long A3d = dup_f32(a23.y);
            cc[0][0] = f32x2_fma(cc[0][0], A0d, bp0);
            cc[0][1] = f32x2_fma(cc[0][1], A0d, bp1);
            cc[1][0] = f32x2_fma(cc[1][0], A1d, bp0);
            cc[1][1] = f32x2_fma(cc[1][1], A1d, bp1);
            cc[2][0] = f32x2_fma(cc[2][0], A2d, bp0);
            cc[2][1] = f32x2_fma(cc[2][1], A2d, bp1);
            cc[3][0] = f32x2_fma(cc[3][0], A3d, bp0);
            cc[3][1] = f32x2_fma(cc[3][1], A3d, bp1);
        }
        if (it < KC / BK - 1) {
            int nxt = cur ^ 1;
            As[nxt][loadK4 + 0][loadRow] = a.x;
            As[nxt][loadK4 + 1][loadRow] = a.y;
            As[nxt][loadK4 + 2][loadRow] = a.z;
            As[nxt][loadK4 + 3][loadRow] = a.w;
            Bs[nxt][loadK4 + 0][loadRow] = b4.x;
            Bs[nxt][loadK4 + 1][loadRow] = b4.y;
            Bs[nxt][loadK4 + 2][loadRow] = b4.z;
            Bs[nxt][loadK4 + 3][loadRow] = b4.w;
            __syncthreads();
        }
    }

    float* og = g_Gk[kz];
#pragma unroll
    for (int i = 0; i < 4; i++) {
        unsigned lo0, hi0, lo1, hi1;
        asm("mov.b64 {%0, %1}, %2;" : "=r"(lo0), "=r"(hi0) : "l"(cc[i][0]));
        asm("mov.b64 {%0, %1}, %2;" : "=r"(lo1), "=r"(hi1) : "l"(cc[i][1]));
        float4 v = make_float4(__uint_as_float(lo0), __uint_as_float(hi0),
                               __uint_as_float(lo1), __uint_as_float(hi1));
        int row = bm * BM + ty4 + i;
        *(float4*)(og + (size_t)row * ROWS + bn * BN + tx4) = v;
    }
}

// ===== K3: per-query loss (320 blocks) + fused final scalar ==================
__global__ void __launch_bounds__(256) k_loss(const float* __restrict__ t_logit,
                                              const float* __restrict__ ori,
                                              const float* __restrict__ l2w,
                                              float* __restrict__ out) {
    __shared__ float red[16];
    __shared__ int s_last;
    __shared__ float s_c[B_], s_ce[B_];
    int q = blockIdx.x, tid = threadIdx.x;
    int lane = tid & 31, warp = tid >> 5;
    int labq = g_lab[q];
    float den = 0.f, num = 0.f;
    for (int n = tid; n < ROWS; n += 256) {
        float g = 0.f;
#pragma unroll
        for (int s = 0; s < SPLITK; s++) g += g_Gk[s][q * ROWS + n];
        float e = __expf(g * 0.0625f);              // TAU = 16
        e = g_val[n] ? e : 0.f;
        den += e;
        if (g_lab[n] == labq) num += e;
    }
#pragma unroll
    for (int o = 16; o; o >>= 1) {
        den += __shfl_down_sync(0xffffffffu, den, o);
        num += __shfl_down_sync(0xffffffffu, num, o);
    }
    if (lane == 0) { red[warp] = den; red[8 + warp] = num; }
    __syncthreads();
    if (tid == 0) {
        float d = 0.f, nm = 0.f;
#pragma unroll
        for (int w = 0; w < 8; w++) { d += red[w]; nm += red[8 + w]; }
        g_per[q] = g_val[q] ? -__logf(nm / d) : 0.f;
        __threadfence();
        int o = atomicAdd(&g_cnt3, 1);
        s_last = (o == ROWS - 1);
    }
    __syncthreads();

    if (s_last) {                                   // last block: final scalar
        __threadfence();
        if (tid < B_) {
            int b = tid;
            float s = 0.f; int c = 0;
            for (int k = 0; k < KH; k++) { int r = b * KH + k; s += g_per[r]; c += g_val[r]; }
            for (int k = 0; k < KL; k++) { int r = HROWS + b * KL + k; s += g_per[r]; c += g_val[r]; }
            s_c[b] = s / (float)c;
            float se = __expf(ori[b * 2 + 0]) + __expf(ori[b * 2 + 1]);
            s_ce[b] = -__logf(__expf(t_logit[0]) / se);
        }
        __syncthreads();
        if (tid == 0) {
            float contr = 0.f, ce = 0.f;
#pragma unroll
            for (int b = 0; b < B_; b++) { contr += s_c[b]; ce += s_ce[b]; }
            contr /= (float)B_;
            ce /= (float)B_;

            unsigned mx = 0u;
            float sum = 0.f;
#pragma unroll
            for (int i = 0; i < B_; i++) { mx = max(mx, g_pmax[i]); sum += g_psum[i]; }
            float gmax = __uint_as_float(mx);
            float meanv = sum / (float)(B_ * N_);
            float Dm = meanv / gmax;
            float l2 = 0.0001f * (1.f - Dm) * (1.f - Dm) * l2w[0];

            out[0] = contr + ce + l2;
            g_cnt3 = 0;                             // reset for next replay
            __threadfence();
        }
    }
}

// ---------------- launch ----------------
extern "C" void kernel_launch(void* const* d_in, const int* in_sizes, int n_in,
                              void* d_out, int out_size) {
    const float* fea     = (const float*)d_in[0];
    const float* score   = (const float*)d_in[1];
    const int*   label   = (const int*)d_in[2];
    const float* t_logit = (const float*)d_in[3];
    const float* ori     = (const float*)d_in[4];
    const float* l2w     = (const float*)d_in[5];
    float* out = (float*)d_out;

    k_selall<<<32, 256>>>(score, label);
    k_gemm<<<25 * SPLITK, 256>>>(fea);
    k_loss<<<ROWS, 256>>>(t_logit, ori, l2w, out);
}

// round 7
// speedup vs baseline: 1.0683x; 1.0683x over previous
#include <cuda_runtime.h>

#define B_    16
#define N_    2048
#define D_    1024
#define KH    15
#define KL    5
#define ROWS  320      // B_*KH + B_*KL
#define HROWS 240      // B_*KH
#define SPLITK 8
#define KC    (D_ / SPLITK)   // 128

#define BM 64
#define BN 64
#define BK 16

// ---------------- scratch (no allocations allowed) ----------------
__device__ unsigned int g_pmax[B_];
__device__ unsigned int g_pmin[B_];
__device__ float        g_psum[B_];
__device__ int          g_idx[ROWS];
__device__ int          g_val[ROWS];
__device__ int          g_lab[ROWS];
__device__ __align__(16) float g_Gk[SPLITK][ROWS * ROWS];
__device__ float        g_per[ROWS];
__device__ int          g_bar1;   // 32-block barrier in k_selall
__device__ int          g_fin1;   // reset helper for k_selall
__device__ int          g_bar2;   // 320-block barrier in k_main
__device__ int          g_cnt3;   // completion counter in k_main

// ---------------- helpers ----------------
__device__ __forceinline__ unsigned long long u64min(unsigned long long a,
                                                     unsigned long long b) {
    return a < b ? a : b;
}

// butterfly min-reduce: every lane ends with the warp minimum
__device__ __forceinline__ unsigned long long warpmin(unsigned long long v) {
#pragma unroll
    for (int o = 16; o; o >>= 1)
        v = u64min(v, __shfl_xor_sync(0xffffffffu, v, o));
    return v;
}

__device__ __forceinline__ unsigned long long f32x2_fma(unsigned long long c,
                                                        unsigned long long a,
                                                        unsigned long long b) {
    asm("fma.rn.f32x2 %0, %1, %2, %0;" : "+l"(c) : "l"(a), "l"(b));
    return c;
}

__device__ __forceinline__ unsigned long long dup_f32(float x) {
    unsigned long long r;
    unsigned u = __float_as_uint(x);
    asm("mov.b64 %0, {%1, %1};" : "=l"(r) : "r"(u));
    return r;
}

__device__ __forceinline__ int ld_cg(const int* p) {
    int v;
    asm volatile("ld.global.cg.b32 %0, [%1];" : "=r"(v) : "l"(p));
    return v;
}

// ================= K1: bag partials + selection (32 blocks) =================
// blocks 0-15: HIGH top-15 of bag bid; blocks 16-31: LOW picks of bag bid-16.
// key = (score_bits << 32) | idx -> lexicographic (score, idx), matching
// jnp stable ascending argsort (score >= 0). Only the selected SET (and the
// even ranks for LOW) matters: order within a bag is loss-invariant.
__global__ void __launch_bounds__(256) k_selall(const float* __restrict__ score,
                                                const int* __restrict__ label) {
    __shared__ unsigned long long s_cand[128];
    __shared__ unsigned s_mx[8], s_mn[8];
    __shared__ float s_sm[8];
    int bid = blockIdx.x, tid = threadIdx.x;
    int lane = tid & 31, warp = tid >> 5;
    bool isHigh = bid < B_;
    int b = isHigh ? bid : bid - B_;

    float sc[8];
#pragma unroll
    for (int i = 0; i < 8; i++) sc[i] = score[b * N_ + tid + i * 256];
    if (tid < 128) s_cand[tid] = ~0ULL;

    // ---- bag partials (HIGH blocks only, one per bag) ----
    if (isHigh) {
        unsigned mx = 0u, mn = 0xFFFFFFFFu;
        float s = 0.f;
#pragma unroll
        for (int i = 0; i < 8; i++) {
            unsigned bb = __float_as_uint(sc[i]);   // score >= 0 -> monotonic
            mx = max(mx, bb);
            mn = min(mn, bb);
            s += sc[i];
        }
#pragma unroll
        for (int o = 16; o; o >>= 1) {
            mx = max(mx, __shfl_down_sync(0xffffffffu, mx, o));
            mn = min(mn, __shfl_down_sync(0xffffffffu, mn, o));
            s += __shfl_down_sync(0xffffffffu, s, o);
        }
        if (lane == 0) { s_mx[warp] = mx; s_mn[warp] = mn; s_sm[warp] = s; }
        __syncthreads();
        if (tid == 0) {
            for (int w = 1; w < 8; w++) {
                mx = max(mx, s_mx[w]); mn = min(mn, s_mn[w]); s += s_sm[w];
            }
            g_pmax[b] = mx; g_pmin[b] = mn; g_psum[b] = s;
        }
    }

    // ---- grid sync over 32 blocks ----
    __syncthreads();
    if (tid == 0) {
        __threadfence();
        atomicAdd(&g_bar1, 1);
        while (ld_cg(&g_bar1) < 32) { __nanosleep(20); }
        __threadfence();
    }
    __syncthreads();

    // ---- global bounds ----
    unsigned mxb = 0u, mnb = 0xFFFFFFFFu;
#pragma unroll
    for (int i = 0; i < B_; i++) {
        mxb = max(mxb, g_pmax[i]);
        mnb = min(mnb, g_pmin[i]);
    }
    float lo, hi;
    if (isHigh) { hi = __uint_as_float(mxb); lo = hi - 0.3f; }
    else        { lo = __uint_as_float(mnb); hi = lo + 1e-9f; }

    unsigned long long key[8];
#pragma unroll
    for (int i = 0; i < 8; i++) {
        key[i] = (sc[i] >= lo && sc[i] <= hi)
            ? (((unsigned long long)__float_as_uint(sc[i]) << 32) |
               (unsigned)(tid + i * 256))
            : ~0ULL;
    }

    int nl = isHigh ? KH : 10;      // rounds (local and merge)

    // ---- phase 1: each warp extracts its local top-nl (shuffle only) ----
    {
        unsigned long long loc = key[0];
#pragma unroll
        for (int i = 1; i < 8; i++) loc = u64min(loc, key[i]);
        for (int t = 0; t < nl; t++) {
            unsigned long long m = warpmin(loc);
            if (m == ~0ULL) break;                    // warp exhausted
            if (lane == 0) s_cand[warp * nl + t] = m;
            if (loc == m) {                           // unique owner pops
#pragma unroll
                for (int i = 0; i < 8; i++) if (key[i] == m) key[i] = ~0ULL;
                loc = key[0];
#pragma unroll
                for (int i = 1; i < 8; i++) loc = u64min(loc, key[i]);
            }
        }
    }
    __syncthreads();

    // ---- phase 2: warp 0 merges the 8*nl candidates ----
    if (warp == 0) {
        unsigned long long cand[4];
#pragma unroll
        for (int j = 0; j < 4; j++) cand[j] = s_cand[lane + 32 * j];
        unsigned long long loc = u64min(u64min(cand[0], cand[1]),
                                        u64min(cand[2], cand[3]));
        int labb = isHigh ? label[b] : 2;
        unsigned long long myv = ~0ULL;               // lane t's winner
        int tend = nl;
        for (int t = 0; t < nl; t++) {
            unsigned long long m = warpmin(loc);
            if (m == ~0ULL) { tend = t; break; }
            if (lane == t) myv = m;
            if (loc == m) {
#pragma unroll
                for (int j = 0; j < 4; j++) if (cand[j] == m) cand[j] = ~0ULL;
                loc = u64min(u64min(cand[0], cand[1]),
                             u64min(cand[2], cand[3]));
            }
        }
        if (isHigh) {
            if (lane < KH) {
                int r = b * KH + lane;
                if (lane < tend) {
                    g_val[r] = 1;
                    g_idx[r] = b * N_ + (int)(myv & 0xFFFFFFFFULL);
                } else { g_val[r] = 0; g_idx[r] = 0; }
                g_lab[r] = labb;
            }
        } else {
            // keep even ranks 0,2,4,6,8 -> slot j gets rank 2j
            unsigned long long ev = __shfl_sync(0xffffffffu, myv,
                                                (lane < KL) ? 2 * lane : 0);
            if (lane < KL) {
                int r = HROWS + b * KL + lane;
                if (2 * lane < tend) {
                    g_val[r] = 1;
                    g_idx[r] = b * N_ + (int)(ev & 0xFFFFFFFFULL);
                } else { g_val[r] = 0; g_idx[r] = 0; }
                g_lab[r] = 2;  // N_CLASSES
            }
        }
    }

    // ---- reset barrier state for next graph replay ----
    if (tid == 0) {
        int o = atomicAdd(&g_fin1, 1);
        if (o == 31) { g_bar1 = 0; g_fin1 = 0; __threadfence(); }
    }
}

// ===== K2: gram GEMM (blocks 0-199) + grid sync + per-query loss + final =====
__global__ void __launch_bounds__(256, 3)
k_main(const float* __restrict__ fea, const float* __restrict__ t_logit,
       const float* __restrict__ ori, const float* __restrict__ l2w,
       float* __restrict__ out) {
    __shared__ __align__(16) float As[2][BK][BM + 2];
    __shared__ __align__(16) float Bs[2][BK][BN + 2];
    __shared__ float red[16];
    __shared__ int s_last;
    __shared__ float s_c[B_], s_ce[B_];
    int bid = blockIdx.x, tid = threadIdx.x;
    int lane = tid & 31, warp = tid >> 5;

    // ---------------- phase 1: gram G = X X^T, fused gather ----------------
    if (bid < 25 * SPLITK) {
        int kz = bid & (SPLITK - 1), tile = bid >> 3;
        int bm = tile / 5, bn = tile % 5;
        int tx = tid & 15, ty = tid >> 4;
        int tx4 = tx * 4, ty4 = ty * 4;

        unsigned long long cc[4][2];
#pragma unroll
        for (int i = 0; i < 4; i++) { cc[i][0] = 0ULL; cc[i][1] = 0ULL; }

        int loadRow = tid >> 2;           // 0..63
        int loadK4  = (tid & 3) * 4;      // 0,4,8,12
        // indirect gather: invalid rows point at row 0; masked in loss phase
        const float* A0 = fea + (size_t)g_idx[bm * BM + loadRow] * D_ + kz * KC + loadK4;
        const float* B0 = fea + (size_t)g_idx[bn * BN + loadRow] * D_ + kz * KC + loadK4;

        float4 a = *(const float4*)A0;
        float4 b4 = *(const float4*)B0;
        As[0][loadK4 + 0][loadRow] = a.x;
        As[0][loadK4 + 1][loadRow] = a.y;
        As[0][loadK4 + 2][loadRow] = a.z;
        As[0][loadK4 + 3][loadRow] = a.w;
        Bs[0][loadK4 + 0][loadRow] = b4.x;
        Bs[0][loadK4 + 1][loadRow] = b4.y;
        Bs[0][loadK4 + 2][loadRow] = b4.z;
        Bs[0][loadK4 + 3][loadRow] = b4.w;
        __syncthreads();

#pragma unroll
        for (int it = 0; it < KC / BK; it++) {
            int cur = it & 1;
            if (it < KC / BK - 1) {                  // prefetch next slab
                a  = *(const float4*)(A0 + (it + 1) * BK);
                b4 = *(const float4*)(B0 + (it + 1) * BK);
            }
#pragma unroll
            for (int k = 0; k < BK; k++) {
                float2 a01 = *(const float2*)&As[cur][k][ty4];
                float2 a23 = *(const float2*)&As[cur][k][ty4 + 2];
                unsigned long long bp0 = *(const unsigned long long*)&Bs[cur][k][tx4];
                unsigned long long bp1 = *(const unsigned long long*)&Bs[cur][k][tx4 + 2];
                unsigned long long A0d = dup_f32(a01.x);
                unsigned long long A1d = dup_f32(a01.y);
                unsigned long long A2d = dup_f32(a23.x);
                unsigned long long A3d = dup_f32(a23.y);
                cc[0][0] = f32x2_fma(cc[0][0], A0d, bp0);
                cc[0][1] = f32x2_fma(cc[0][1], A0d, bp1);
                cc[1][0] = f32x2_fma(cc[1][0], A1d, bp0);
                cc[1][1] = f32x2_fma(cc[1][1], A1d, bp1);
                cc[2][0] = f32x2_fma(cc[2][0], A2d, bp0);
                cc[2][1] = f32x2_fma(cc[2][1], A2d, bp1);
                cc[3][0] = f32x2_fma(cc[3][0], A3d, bp0);
                cc[3][1] = f32x2_fma(cc[3][1], A3d, bp1);
            }
            if (it < KC / BK - 1) {
                int nxt = cur ^ 1;
                As[nxt][loadK4 + 0][loadRow] = a.x;
                As[nxt][loadK4 + 1][loadRow] = a.y;
                As[nxt][loadK4 + 2][loadRow] = a.z;
                As[nxt][loadK4 + 3][loadRow] = a.w;
                Bs[nxt][loadK4 + 0][loadRow] = b4.x;
                Bs[nxt][loadK4 + 1][loadRow] = b4.y;
                Bs[nxt][loadK4 + 2][loadRow] = b4.z;
                Bs[nxt][loadK4 + 3][loadRow] = b4.w;
                __syncthreads();
            }
        }

        float* og = g_Gk[kz];
#pragma unroll
        for (int i = 0; i < 4; i++) {
            unsigned lo0, hi0, lo1, hi1;
            asm("mov.b64 {%0, %1}, %2;" : "=r"(lo0), "=r"(hi0) : "l"(cc[i][0]));
            asm("mov.b64 {%0, %1}, %2;" : "=r"(lo1), "=r"(hi1) : "l"(cc[i][1]));
            float4 v = make_float4(__uint_as_float(lo0), __uint_as_float(hi0),
                                   __uint_as_float(lo1), __uint_as_float(hi1));
            int row = bm * BM + ty4 + i;
            *(float4*)(og + (size_t)row * ROWS + bn * BN + tx4) = v;
        }
    }

    // ---------------- grid sync over 320 blocks ----------------
    __syncthreads();
    if (tid == 0) {
        __threadfence();
        atomicAdd(&g_bar2, 1);
        while (ld_cg(&g_bar2) < ROWS) { __nanosleep(20); }
        __threadfence();
    }
    __syncthreads();

    // ---------------- phase 2: per-query loss (all 320 blocks) -------------
    {
        int q = bid;
        int labq = g_lab[q];
        float den = 0.f, num = 0.f;
        for (int n = tid; n < ROWS; n += 256) {
            float g = 0.f;
#pragma unroll
            for (int s = 0; s < SPLITK; s++) g += g_Gk[s][q * ROWS + n];
            float e = __expf(g * 0.0625f);          // TAU = 16
            e = g_val[n] ? e : 0.f;
            den += e;
            if (g_lab[n] == labq) num += e;
        }
#pragma unroll
        for (int o = 16; o; o >>= 1) {
            den += __shfl_down_sync(0xffffffffu, den, o);
            num += __shfl_down_sync(0xffffffffu, num, o);
        }
        if (lane == 0) { red[warp] = den; red[8 + warp] = num; }
        __syncthreads();
        if (tid == 0) {
            float d = 0.f, nm = 0.f;
#pragma unroll
            for (int w = 0; w < 8; w++) { d += red[w]; nm += red[8 + w]; }
            g_per[q] = g_val[q] ? -__logf(nm / d) : 0.f;
            __threadfence();
            int o = atomicAdd(&g_cnt3, 1);
            s_last = (o == ROWS - 1);
        }
        __syncthreads();
    }

    // ---------------- last block: final scalar + state reset ----------------
    if (s_last) {
        __threadfence();
        if (tid < B_) {
            int b = tid;
            float s = 0.f; int c = 0;
            for (int k = 0; k < KH; k++) { int r = b * KH + k; s += g_per[r]; c += g_val[r]; }
            for (int k = 0; k < KL; k++) { int r = HROWS + b * KL + k; s += g_per[r]; c += g_val[r]; }
            s_c[b] = s / (float)c;
            float se = __expf(ori[b * 2 + 0]) + __expf(ori[b * 2 + 1]);
            s_ce[b] = -__logf(__expf(t_logit[0]) / se);
        }
        __syncthreads();
        if (tid == 0) {
            float contr = 0.f, ce = 0.f;
#pragma unroll
            for (int b = 0; b < B_; b++) { contr += s_c[b]; ce += s_ce[b]; }
            contr /= (float)B_;
            ce /= (float)B_;

            unsigned mx = 0u;
            float sum = 0.f;
#pragma unroll
            for (int i = 0; i < B_; i++) { mx = max(mx, g_pmax[i]); sum += g_psum[i]; }
            float gmax = __uint_as_float(mx);
            float meanv = sum / (float)(B_ * N_);
            float Dm = meanv / gmax;
            float l2 = 0.0001f * (1.f - Dm) * (1.f - Dm) * l2w[0];

            out[0] = contr + ce + l2;
            // all 320 blocks have passed both the barrier and the counter:
            g_bar2 = 0;
            g_cnt3 = 0;
            __threadfence();
        }
    }
}

// ---------------- launch ----------------
extern "C" void kernel_launch(void* const* d_in, const int* in_sizes, int n_in,
                              void* d_out, int out_size) {
    const float* fea     = (const float*)d_in[0];
    const float* score   = (const float*)d_in[1];
    const int*   label   = (const int*)d_in[2];
    const float* t_logit = (const float*)d_in[3];
    const float* ori     = (const float*)d_in[4];
    const float* l2w     = (const float*)d_in[5];
    float* out = (float*)d_out;

    k_selall<<<32, 256>>>(score, label);
    k_main<<<ROWS, 256>>>(fea, t_logit, ori, l2w, out);
}

// round 8
// speedup vs baseline: 1.1373x; 1.0645x over previous
#include <cuda_runtime.h>

#define B_    16
#define N_    2048
#define D_    1024
#define KH    15
#define KL    5
#define ROWS  320      // B_*KH + B_*KL
#define HROWS 240      // B_*KH
#define SPLITK 16
#define KC    (D_ / SPLITK)   // 64

#define BM 64
#define BN 64
#define BK 16

// ---------------- scratch (no allocations allowed) ----------------
__device__ unsigned int g_pmax[B_];
__device__ unsigned int g_pmin[B_];
__device__ float        g_psum[B_];
__device__ int          g_idx[ROWS];
__device__ int          g_val[ROWS];
__device__ int          g_lab[ROWS];
__device__ __align__(16) float g_Gk[SPLITK][ROWS * ROWS];
__device__ float        g_per[ROWS];
__device__ int          g_bar1;   // 32-block barrier in k_selall
__device__ int          g_fin1;   // reset helper for k_selall
__device__ int          g_cnt3;   // completion counter in k_loss

// ---------------- helpers ----------------
__device__ __forceinline__ unsigned long long u64min(unsigned long long a,
                                                     unsigned long long b) {
    return a < b ? a : b;
}

// butterfly min-reduce: every lane ends with the warp minimum
__device__ __forceinline__ unsigned long long warpmin(unsigned long long v) {
#pragma unroll
    for (int o = 16; o; o >>= 1)
        v = u64min(v, __shfl_xor_sync(0xffffffffu, v, o));
    return v;
}

__device__ __forceinline__ unsigned long long f32x2_fma(unsigned long long c,
                                                        unsigned long long a,
                                                        unsigned long long b) {
    asm("fma.rn.f32x2 %0, %1, %2, %0;" : "+l"(c) : "l"(a), "l"(b));
    return c;
}

__device__ __forceinline__ unsigned long long dup_f32(float x) {
    unsigned long long r;
    unsigned u = __float_as_uint(x);
    asm("mov.b64 %0, {%1, %1};" : "=l"(r) : "r"(u));
    return r;
}

__device__ __forceinline__ int ld_cg(const int* p) {
    int v;
    asm volatile("ld.global.cg.b32 %0, [%1];" : "=r"(v) : "l"(p));
    return v;
}

// ================= K1: bag partials + selection (32 blocks) =================
// blocks 0-15: HIGH top-15 of bag bid; blocks 16-31: LOW picks of bag bid-16.
// key = (score_bits << 32) | idx -> lexicographic (score, idx), matching
// jnp stable ascending argsort (score >= 0). Only the selected SET (and the
// even ranks for LOW) matters: order within a bag is loss-invariant.
__global__ void __launch_bounds__(256) k_selall(const float* __restrict__ score,
                                                const int* __restrict__ label) {
    __shared__ unsigned long long s_cand[128];
    __shared__ unsigned s_mx[8], s_mn[8];
    __shared__ float s_sm[8];
    int bid = blockIdx.x, tid = threadIdx.x;
    int lane = tid & 31, warp = tid >> 5;
    bool isHigh = bid < B_;
    int b = isHigh ? bid : bid - B_;

    float sc[8];
#pragma unroll
    for (int i = 0; i < 8; i++) sc[i] = score[b * N_ + tid + i * 256];
    if (tid < 128) s_cand[tid] = ~0ULL;

    // ---- bag partials (HIGH blocks only, one per bag) ----
    if (isHigh) {
        unsigned mx = 0u, mn = 0xFFFFFFFFu;
        float s = 0.f;
#pragma unroll
        for (int i = 0; i < 8; i++) {
            unsigned bb = __float_as_uint(sc[i]);   // score >= 0 -> monotonic
            mx = max(mx, bb);
            mn = min(mn, bb);
            s += sc[i];
        }
#pragma unroll
        for (int o = 16; o; o >>= 1) {
            mx = max(mx, __shfl_down_sync(0xffffffffu, mx, o));
            mn = min(mn, __shfl_down_sync(0xffffffffu, mn, o));
            s += __shfl_down_sync(0xffffffffu, s, o);
        }
        if (lane == 0) { s_mx[warp] = mx; s_mn[warp] = mn; s_sm[warp] = s; }
        __syncthreads();
        if (tid == 0) {
            for (int w = 1; w < 8; w++) {
                mx = max(mx, s_mx[w]); mn = min(mn, s_mn[w]); s += s_sm[w];
            }
            g_pmax[b] = mx; g_pmin[b] = mn; g_psum[b] = s;
        }
    }

    // ---- grid sync over 32 blocks ----
    __syncthreads();
    if (tid == 0) {
        __threadfence();
        atomicAdd(&g_bar1, 1);
        while (ld_cg(&g_bar1) < 32) { __nanosleep(20); }
        __threadfence();
    }
    __syncthreads();

    // ---- global bounds ----
    unsigned mxb = 0u, mnb = 0xFFFFFFFFu;
#pragma unroll
    for (int i = 0; i < B_; i++) {
        mxb = max(mxb, g_pmax[i]);
        mnb = min(mnb, g_pmin[i]);
    }
    float lo, hi;
    if (isHigh) { hi = __uint_as_float(mxb); lo = hi - 0.3f; }
    else        { lo = __uint_as_float(mnb); hi = lo + 1e-9f; }

    unsigned long long key[8];
#pragma unroll
    for (int i = 0; i < 8; i++) {
        key[i] = (sc[i] >= lo && sc[i] <= hi)
            ? (((unsigned long long)__float_as_uint(sc[i]) << 32) |
               (unsigned)(tid + i * 256))
            : ~0ULL;
    }

    int nl = isHigh ? KH : 10;      // rounds (local and merge)

    // ---- phase 1: each warp extracts its local top-nl (shuffle only) ----
    {
        unsigned long long loc = key[0];
#pragma unroll
        for (int i = 1; i < 8; i++) loc = u64min(loc, key[i]);
        for (int t = 0; t < nl; t++) {
            unsigned long long m = warpmin(loc);
            if (m == ~0ULL) break;                    // warp exhausted
            if (lane == 0) s_cand[warp * nl + t] = m;
            if (loc == m) {                           // unique owner pops
#pragma unroll
                for (int i = 0; i < 8; i++) if (key[i] == m) key[i] = ~0ULL;
                loc = key[0];
#pragma unroll
                for (int i = 1; i < 8; i++) loc = u64min(loc, key[i]);
            }
        }
    }
    __syncthreads();

    // ---- phase 2: warp 0 merges the 8*nl candidates ----
    if (warp == 0) {
        unsigned long long cand[4];
#pragma unroll
        for (int j = 0; j < 4; j++) cand[j] = s_cand[lane + 32 * j];
        unsigned long long loc = u64min(u64min(cand[0], cand[1]),
                                        u64min(cand[2], cand[3]));
        int labb = isHigh ? label[b] : 2;
        unsigned long long myv = ~0ULL;               // lane t's winner
        int tend = nl;
        for (int t = 0; t < nl; t++) {
            unsigned long long m = warpmin(loc);
            if (m == ~0ULL) { tend = t; break; }
            if (lane == t) myv = m;
            if (loc == m) {
#pragma unroll
                for (int j = 0; j < 4; j++) if (cand[j] == m) cand[j] = ~0ULL;
                loc = u64min(u64min(cand[0], cand[1]),
                             u64min(cand[2], cand[3]));
            }
        }
        if (isHigh) {
            if (lane < KH) {
                int r = b * KH + lane;
                if (lane < tend) {
                    g_val[r] = 1;
                    g_idx[r] = b * N_ + (int)(myv & 0xFFFFFFFFULL);
                } else { g_val[r] = 0; g_idx[r] = 0; }
                g_lab[r] = labb;
            }
        } else {
            // keep even ranks 0,2,4,6,8 -> slot j gets rank 2j
            unsigned long long ev = __shfl_sync(0xffffffffu, myv,
                                                (lane < KL) ? 2 * lane : 0);
            if (lane < KL) {
                int r = HROWS + b * KL + lane;
                if (2 * lane < tend) {
                    g_val[r] = 1;
                    g_idx[r] = b * N_ + (int)(ev & 0xFFFFFFFFULL);
                } else { g_val[r] = 0; g_idx[r] = 0; }
                g_lab[r] = 2;  // N_CLASSES
            }
        }
    }

    // ---- reset barrier state for next graph replay ----
    if (tid == 0) {
        int o = atomicAdd(&g_fin1, 1);
        if (o == 31) { g_bar1 = 0; g_fin1 = 0; __threadfence(); }
    }
}

// ===== K2: gram G = X X^T (320x320, K=1024), fused gather, double-buffered ===
__global__ void __launch_bounds__(256) k_gemm(const float* __restrict__ fea) {
    // pad rows to 68 floats so &As[k][4*t] stays 16B-aligned for LDS.128
    __shared__ __align__(16) float As[2][BK][BM + 4];
    __shared__ __align__(16) float Bs[2][BK][BN + 4];
    int kz = blockIdx.x & (SPLITK - 1), tile = blockIdx.x / SPLITK;
    int bm = tile / 5, bn = tile % 5;
    int tid = threadIdx.x;
    int tx = tid & 15, ty = tid >> 4;
    int tx4 = tx * 4, ty4 = ty * 4;

    unsigned long long cc[4][2];
#pragma unroll
    for (int i = 0; i < 4; i++) { cc[i][0] = 0ULL; cc[i][1] = 0ULL; }

    int loadRow = tid >> 2;           // 0..63
    int loadK4  = (tid & 3) * 4;      // 0,4,8,12
    // indirect gather: invalid rows point at row 0; masked in k_loss
    const float* A0 = fea + (size_t)g_idx[bm * BM + loadRow] * D_ + kz * KC + loadK4;
    const float* B0 = fea + (size_t)g_idx[bn * BN + loadRow] * D_ + kz * KC + loadK4;

    float4 a = *(const float4*)A0;
    float4 b4 = *(const float4*)B0;
    As[0][loadK4 + 0][loadRow] = a.x;
    As[0][loadK4 + 1][loadRow] = a.y;
    As[0][loadK4 + 2][loadRow] = a.z;
    As[0][loadK4 + 3][loadRow] = a.w;
    Bs[0][loadK4 + 0][loadRow] = b4.x;
    Bs[0][loadK4 + 1][loadRow] = b4.y;
    Bs[0][loadK4 + 2][loadRow] = b4.z;
    Bs[0][loadK4 + 3][loadRow] = b4.w;
    __syncthreads();

#pragma unroll
    for (int it = 0; it < KC / BK; it++) {
        int cur = it & 1;
        if (it < KC / BK - 1) {                      // prefetch next slab
            a  = *(const float4*)(A0 + (it + 1) * BK);
            b4 = *(const float4*)(B0 + (it + 1) * BK);
        }
#pragma unroll
        for (int k = 0; k < BK; k++) {
            float4 av = *(const float4*)&As[cur][k][ty4];    // LDS.128
            float4 bv = *(const float4*)&Bs[cur][k][tx4];    // LDS.128
            unsigned long long bp0, bp1;
            asm("mov.b64 %0, {%1, %2};" : "=l"(bp0)
                : "r"(__float_as_uint(bv.x)), "r"(__float_as_uint(bv.y)));
            asm("mov.b64 %0, {%1, %2};" : "=l"(bp1)
                : "r"(__float_as_uint(bv.z)), "r"(__float_as_uint(bv.w)));
            unsigned long long A0d = dup_f32(av.x);
            unsigned long long A1d = dup_f32(av.y);
            unsigned long long A2d = dup_f32(av.z);
            unsigned long long A3d = dup_f32(av.w);
            cc[0][0] = f32x2_fma(cc[0][0], A0d, bp0);
            cc[0][1] = f32x2_fma(cc[0][1], A0d, bp1);
            cc[1][0] = f32x2_fma(cc[1][0], A1d, bp0);
            cc[1][1] = f32x2_fma(cc[1][1], A1d, bp1);
            cc[2][0] = f32x2_fma(cc[2][0], A2d, bp0);
            cc[2][1] = f32x2_fma(cc[2][1], A2d, bp1);
            cc[3][0] = f32x2_fma(cc[3][0], A3d, bp0);
            cc[3][1] = f32x2_fma(cc[3][1], A3d, bp1);
        }
        if (it < KC / BK - 1) {
            int nxt = cur ^ 1;
            As[nxt][loadK4 + 0][loadRow] = a.x;
            As[nxt][loadK4 + 1][loadRow] = a.y;
            As[nxt][loadK4 + 2][loadRow] = a.z;
            As[nxt][loadK4 + 3][loadRow] = a.w;
            Bs[nxt][loadK4 + 0][loadRow] = b4.x;
            Bs[nxt][loadK4 + 1][loadRow] = b4.y;
            Bs[nxt][loadK4 + 2][loadRow] = b4.z;
            Bs[nxt][loadK4 + 3][loadRow] = b4.w;
            __syncthreads();
        }
    }

    float* og = g_Gk[kz];
#pragma unroll
    for (int i = 0; i < 4; i++) {
        unsigned lo0, hi0, lo1, hi1;
        asm("mov.b64 {%0, %1}, %2;" : "=r"(lo0), "=r"(hi0) : "l"(cc[i][0]));
        asm("mov.b64 {%0, %1}, %2;" : "=r"(lo1), "=r"(hi1) : "l"(cc[i][1]));
        float4 v = make_float4(__uint_as_float(lo0), __uint_as_float(hi0),
                               __uint_as_float(lo1), __uint_as_float(hi1));
        int row = bm * BM + ty4 + i;
        *(float4*)(og + (size_t)row * ROWS + bn * BN + tx4) = v;
    }
}

// ===== K3: per-query loss (320 blocks) + fused final scalar ==================
__global__ void __launch_bounds__(256) k_loss(const float* __restrict__ t_logit,
                                              const float* __restrict__ ori,
                                              const float* __restrict__ l2w,
                                              float* __restrict__ out) {
    __shared__ float red[16];
    __shared__ int s_last;
    __shared__ float s_c[B_], s_ce[B_];
    int q = blockIdx.x, tid = threadIdx.x;
    int lane = tid & 31, warp = tid >> 5;
    int labq = g_lab[q];
    float den = 0.f, num = 0.f;
    for (int n = tid; n < ROWS; n += 256) {
        float g = 0.f;
#pragma unroll
        for (int s = 0; s < SPLITK; s++) g += g_Gk[s][q * ROWS + n];
        float e = __expf(g * 0.0625f);              // TAU = 16
        e = g_val[n] ? e : 0.f;
        den += e;
        if (g_lab[n] == labq) num += e;
    }
#pragma unroll
    for (int o = 16; o; o >>= 1) {
        den += __shfl_down_sync(0xffffffffu, den, o);
        num += __shfl_down_sync(0xffffffffu, num, o);
    }
    if (lane == 0) { red[warp] = den; red[8 + warp] = num; }
    __syncthreads();
    if (tid == 0) {
        float d = 0.f, nm = 0.f;
#pragma unroll
        for (int w = 0; w < 8; w++) { d += red[w]; nm += red[8 + w]; }
        g_per[q] = g_val[q] ? -__logf(nm / d) : 0.f;
        __threadfence();
        int o = atomicAdd(&g_cnt3, 1);
        s_last = (o == ROWS - 1);
    }
    __syncthreads();

    if (s_last) {                                   // last block: final scalar
        __threadfence();
        if (tid < B_) {
            int b = tid;
            float s = 0.f; int c = 0;
            for (int k = 0; k < KH; k++) { int r = b * KH + k; s += g_per[r]; c += g_val[r]; }
            for (int k = 0; k < KL; k++) { int r = HROWS + b * KL + k; s += g_per[r]; c += g_val[r]; }
            s_c[b] = s / (float)c;
            float se = __expf(ori[b * 2 + 0]) + __expf(ori[b * 2 + 1]);
            s_ce[b] = -__logf(__expf(t_logit[0]) / se);
        }
        __syncthreads();
        if (tid == 0) {
            float contr = 0.f, ce = 0.f;
#pragma unroll
            for (int b = 0; b < B_; b++) { contr += s_c[b]; ce += s_ce[b]; }
            contr /= (float)B_;
            ce /= (float)B_;

            unsigned mx = 0u;
            float sum = 0.f;
#pragma unroll
            for (int i = 0; i < B_; i++) { mx = max(mx, g_pmax[i]); sum += g_psum[i]; }
            float gmax = __uint_as_float(mx);
            float meanv = sum / (float)(B_ * N_);
            float Dm = meanv / gmax;
            float l2 = 0.0001f * (1.f - Dm) * (1.f - Dm) * l2w[0];

            out[0] = contr + ce + l2;
            g_cnt3 = 0;                             // reset for next replay
            __threadfence();
        }
    }
}

// ---------------- launch ----------------
extern "C" void kernel_launch(void* const* d_in, const int* in_sizes, int n_in,
                              void* d_out, int out_size) {
    const float* fea     = (const float*)d_in[0];
    const float* score   = (const float*)d_in[1];
    const int*   label   = (const int*)d_in[2];
    const float* t_logit = (const float*)d_in[3];
    const float* ori     = (const float*)d_in[4];
    const float* l2w     = (const float*)d_in[5];
    float* out = (float*)d_out;

    k_selall<<<32, 256>>>(score, label);
    k_gemm<<<25 * SPLITK, 256>>>(fea);
    k_loss<<<ROWS, 256>>>(t_logit, ori, l2w, out);
}

// round 10
// speedup vs baseline: 1.2171x; 1.0702x over previous
#include <cuda_runtime.h>

#define B_    16
#define N_    2048
#define D_    1024
#define KH    15
#define KL    5
#define ROWS  320      // B_*KH + B_*KL
#define HROWS 240      // B_*KH
#define SPLITK 16
#define KC    (D_ / SPLITK)   // 64

#define BM 64
#define BN 64
#define BK 16

// ---------------- scratch (no allocations allowed) ----------------
__device__ unsigned int g_pmax[B_];
__device__ float        g_psum[B_];
__device__ int          g_idx[ROWS];
__device__ int          g_val[ROWS];
__device__ int          g_lab[ROWS];
__device__ __align__(16) float g_Gk[SPLITK][ROWS * ROWS];
__device__ float        g_per[ROWS];
__device__ int          g_cnt3;   // completion counter in k_loss

// ---------------- helpers ----------------
__device__ __forceinline__ unsigned long long u64min(unsigned long long a,
                                                     unsigned long long b) {
    return a < b ? a : b;
}

// butterfly min-reduce: every lane ends with the warp minimum
__device__ __forceinline__ unsigned long long warpmin(unsigned long long v) {
#pragma unroll
    for (int o = 16; o; o >>= 1)
        v = u64min(v, __shfl_xor_sync(0xffffffffu, v, o));
    return v;
}

__device__ __forceinline__ unsigned long long f32x2_fma(unsigned long long c,
                                                        unsigned long long a,
                                                        unsigned long long b) {
    asm("fma.rn.f32x2 %0, %1, %2, %0;" : "+l"(c) : "l"(a), "l"(b));
    return c;
}

__device__ __forceinline__ unsigned long long dup_f32(float x) {
    unsigned long long r;
    unsigned u = __float_as_uint(x);
    asm("mov.b64 %0, {%1, %1};" : "=l"(r) : "r"(u));
    return r;
}

// ================= K1: selection (32 blocks, NO grid barrier) ================
// blocks 0-15: HIGH top-15 of bag bid; blocks 16-31: LOW picks of bag bid-16.
// Every block computes the global score bound itself by streaming all B_*N_
// scores (float4), so no cross-block communication is needed.
// key = (score_bits << 32) | idx -> lexicographic (score, idx), matching
// jnp stable ascending argsort (score >= 0). Only the selected SET (and the
// even ranks for LOW) matters: order within a bag is loss-invariant.
__global__ void __launch_bounds__(256) k_selall(const float* __restrict__ score,
                                                const int* __restrict__ label) {
    __shared__ unsigned long long s_cand[128];
    __shared__ unsigned s_r[8];
    __shared__ float    s_bsum[8];      // dedicated: per-warp bag sum
    __shared__ unsigned s_bmax[8];      // dedicated: per-warp bag max
    int bid = blockIdx.x, tid = threadIdx.x;
    int lane = tid & 31, warp = tid >> 5;
    bool isHigh = bid < B_;
    int b = isHigh ? bid : bid - B_;

    // ---- stream ALL scores, reduce global bound (max for HIGH, min for LOW)
    const float4* s4 = (const float4*)score;
    unsigned gb = isHigh ? 0u : 0xFFFFFFFFu;        // score >= 0 -> bits monotonic
#pragma unroll 8
    for (int i = 0; i < (B_ * N_ / 4) / 256; i++) {  // 32 float4 per thread
        float4 v = s4[tid + i * 256];
        unsigned b0 = __float_as_uint(v.x), b1 = __float_as_uint(v.y);
        unsigned b2 = __float_as_uint(v.z), b3 = __float_as_uint(v.w);
        if (isHigh) gb = max(max(gb, b0), max(b1, max(b2, b3)));
        else        gb = min(min(gb, b0), min(b1, min(b2, b3)));
    }
#pragma unroll
    for (int o = 16; o; o >>= 1) {
        unsigned t = __shfl_xor_sync(0xffffffffu, gb, o);
        gb = isHigh ? max(gb, t) : min(gb, t);
    }
    if (lane == 0) s_r[warp] = gb;

    // ---- own-bag scalar loads for extraction ----
    float sc[8];
#pragma unroll
    for (int i = 0; i < 8; i++) sc[i] = score[b * N_ + tid + i * 256];
    if (tid < 128) s_cand[tid] = ~0ULL;

    // ---- bag partials for the final L2 term (HIGH blocks only) ----
    if (isHigh) {
        float s = 0.f;
        unsigned mx = 0u;
#pragma unroll
        for (int i = 0; i < 8; i++) {
            s += sc[i];
            mx = max(mx, __float_as_uint(sc[i]));
        }
#pragma unroll
        for (int o = 16; o; o >>= 1) {
            s += __shfl_down_sync(0xffffffffu, s, o);
            mx = max(mx, __shfl_down_sync(0xffffffffu, mx, o));
        }
        if (lane == 0) { s_bsum[warp] = s; s_bmax[warp] = mx; }
    }
    __syncthreads();

    unsigned gbound = isHigh ? 0u : 0xFFFFFFFFu;
#pragma unroll
    for (int w = 0; w < 8; w++)
        gbound = isHigh ? max(gbound, s_r[w]) : min(gbound, s_r[w]);

    if (isHigh && tid == 0) {
        float s = 0.f;
        unsigned mx = 0u;
#pragma unroll
        for (int w = 0; w < 8; w++) {
            s += s_bsum[w];
            mx = max(mx, s_bmax[w]);
        }
        g_psum[b] = s;
        g_pmax[b] = mx;
    }

    float lo, hi;
    if (isHigh) { hi = __uint_as_float(gbound); lo = hi - 0.3f; }
    else        { lo = __uint_as_float(gbound); hi = lo + 1e-9f; }

    unsigned long long key[8];
#pragma unroll
    for (int i = 0; i < 8; i++) {
        key[i] = (sc[i] >= lo && sc[i] <= hi)
            ? (((unsigned long long)__float_as_uint(sc[i]) << 32) |
               (unsigned)(tid + i * 256))
            : ~0ULL;
    }

    int nl = isHigh ? KH : 10;      // rounds (local and merge)

    // ---- phase 1: each warp extracts its local top-nl (shuffle only) ----
    {
        unsigned long long loc = key[0];
#pragma unroll
        for (int i = 1; i < 8; i++) loc = u64min(loc, key[i]);
        for (int t = 0; t < nl; t++) {
            unsigned long long m = warpmin(loc);
            if (m == ~0ULL) break;                    // warp exhausted
            if (lane == 0) s_cand[warp * nl + t] = m;
            if (loc == m) {                           // unique owner pops
#pragma unroll
                for (int i = 0; i < 8; i++) if (key[i] == m) key[i] = ~0ULL;
                loc = key[0];
#pragma unroll
                for (int i = 1; i < 8; i++) loc = u64min(loc, key[i]);
            }
        }
    }
    __syncthreads();

    // ---- phase 2: warp 0 merges the 8*nl candidates ----
    if (warp == 0) {
        unsigned long long cand[4];
#pragma unroll
        for (int j = 0; j < 4; j++) cand[j] = s_cand[lane + 32 * j];
        unsigned long long loc = u64min(u64min(cand[0], cand[1]),
                                        u64min(cand[2], cand[3]));
        int labb = isHigh ? label[b] : 2;
        unsigned long long myv = ~0ULL;               // lane t's winner
        int tend = nl;
        for (int t = 0; t < nl; t++) {
            unsigned long long m = warpmin(loc);
            if (m == ~0ULL) { tend = t; break; }
            if (lane == t) myv = m;
            if (loc == m) {
#pragma unroll
                for (int j = 0; j < 4; j++) if (cand[j] == m) cand[j] = ~0ULL;
                loc = u64min(u64min(cand[0], cand[1]),
                             u64min(cand[2], cand[3]));
            }
        }
        if (isHigh) {
            if (lane < KH) {
                int r = b * KH + lane;
                if (lane < tend) {
                    g_val[r] = 1;
                    g_idx[r] = b * N_ + (int)(myv & 0xFFFFFFFFULL);
                } else { g_val[r] = 0; g_idx[r] = 0; }
                g_lab[r] = labb;
            }
        } else {
            // keep even ranks 0,2,4,6,8 -> slot j gets rank 2j
            unsigned long long ev = __shfl_sync(0xffffffffu, myv,
                                                (lane < KL) ? 2 * lane : 0);
            if (lane < KL) {
                int r = HROWS + b * KL + lane;
                if (2 * lane < tend) {
                    g_val[r] = 1;
                    g_idx[r] = b * N_ + (int)(ev & 0xFFFFFFFFULL);
                } else { g_val[r] = 0; g_idx[r] = 0; }
                g_lab[r] = 2;  // N_CLASSES
            }
        }
    }
}

// ===== K2: gram G = X X^T (320x320, K=1024), fused gather, double-buffered ===
__global__ void __launch_bounds__(256) k_gemm(const float* __restrict__ fea) {
    // pad rows to 68 floats so &As[k][4*t] stays 16B-aligned for LDS.128
    __shared__ __align__(16) float As[2][BK][BM + 4];
    __shared__ __align__(16) float Bs[2][BK][BN + 4];
    int kz = blockIdx.x & (SPLITK - 1), tile = blockIdx.x / SPLITK;
    int bm = tile / 5, bn = tile % 5;
    int tid = threadIdx.x;
    int tx = tid & 15, ty = tid >> 4;
    int tx4 = tx * 4, ty4 = ty * 4;

    unsigned long long cc[4][2];
#pragma unroll
    for (int i = 0; i < 4; i++) { cc[i][0] = 0ULL; cc[i][1] = 0ULL; }

    int loadRow = tid >> 2;           // 0..63
    int loadK4  = (tid & 3) * 4;      // 0,4,8,12
    // indirect gather: invalid rows point at row 0; masked in k_loss
    const float* A0 = fea + (size_t)g_idx[bm * BM + loadRow] * D_ + kz * KC + loadK4;
    const float* B0 = fea + (size_t)g_idx[bn * BN + loadRow] * D_ + kz * KC + loadK4;

    float4 a = *(const float4*)A0;
    float4 b4 = *(const float4*)B0;
    As[0][loadK4 + 0][loadRow] = a.x;
    As[0][loadK4 + 1][loadRow] = a.y;
    As[0][loadK4 + 2][loadRow] = a.z;
    As[0][loadK4 + 3][loadRow] = a.w;
    Bs[0][loadK4 + 0][loadRow] = b4.x;
    Bs[0][loadK4 + 1][loadRow] = b4.y;
    Bs[0][loadK4 + 2][loadRow] = b4.z;
    Bs[0][loadK4 + 3][loadRow] = b4.w;
    __syncthreads();

#pragma unroll
    for (int it = 0; it < KC / BK; it++) {
        int cur = it & 1;
        if (it < KC / BK - 1) {                      // prefetch next slab
            a  = *(const float4*)(A0 + (it + 1) * BK);
            b4 = *(const float4*)(B0 + (it + 1) * BK);
        }
#pragma unroll
        for (int k = 0; k < BK; k++) {
            float4 av = *(const float4*)&As[cur][k][ty4];    // LDS.128
            float4 bv = *(const float4*)&Bs[cur][k][tx4];    // LDS.128
            unsigned long long bp0, bp1;
            asm("mov.b64 %0, {%1, %2};" : "=l"(bp0)
                : "r"(__float_as_uint(bv.x)), "r"(__float_as_uint(bv.y)));
            asm("mov.b64 %0, {%1, %2};" : "=l"(bp1)
                : "r"(__float_as_uint(bv.z)), "r"(__float_as_uint(bv.w)));
            unsigned long long A0d = dup_f32(av.x);
            unsigned long long A1d = dup_f32(av.y);
            unsigned long long A2d = dup_f32(av.z);
            unsigned long long A3d = dup_f32(av.w);
            cc[0][0] = f32x2_fma(cc[0][0], A0d, bp0);
            cc[0][1] = f32x2_fma(cc[0][1], A0d, bp1);
            cc[1][0] = f32x2_fma(cc[1][0], A1d, bp0);
            cc[1][1] = f32x2_fma(cc[1][1], A1d, bp1);
            cc[2][0] = f32x2_fma(cc[2][0], A2d, bp0);
            cc[2][1] = f32x2_fma(cc[2][1], A2d, bp1);
            cc[3][0] = f32x2_fma(cc[3][0], A3d, bp0);
            cc[3][1] = f32x2_fma(cc[3][1], A3d, bp1);
        }
        if (it < KC / BK - 1) {
            int nxt = cur ^ 1;
            As[nxt][loadK4 + 0][loadRow] = a.x;
            As[nxt][loadK4 + 1][loadRow] = a.y;
            As[nxt][loadK4 + 2][loadRow] = a.z;
            As[nxt][loadK4 + 3][loadRow] = a.w;
            Bs[nxt][loadK4 + 0][loadRow] = b4.x;
            Bs[nxt][loadK4 + 1][loadRow] = b4.y;
            Bs[nxt][loadK4 + 2][loadRow] = b4.z;
            Bs[nxt][loadK4 + 3][loadRow] = b4.w;
            __syncthreads();
        }
    }

    float* og = g_Gk[kz];
#pragma unroll
    for (int i = 0; i < 4; i++) {
        unsigned lo0, hi0, lo1, hi1;
        asm("mov.b64 {%0, %1}, %2;" : "=r"(lo0), "=r"(hi0) : "l"(cc[i][0]));
        asm("mov.b64 {%0, %1}, %2;" : "=r"(lo1), "=r"(hi1) : "l"(cc[i][1]));
        float4 v = make_float4(__uint_as_float(lo0), __uint_as_float(hi0),
                               __uint_as_float(lo1), __uint_as_float(hi1));
        int row = bm * BM + ty4 + i;
        *(float4*)(og + (size_t)row * ROWS + bn * BN + tx4) = v;
    }
}

// ===== K3: per-query loss (320 blocks) + fused final scalar ==================
__global__ void __launch_bounds__(256) k_loss(const float* __restrict__ t_logit,
                                              const float* __restrict__ ori,
                                              const float* __restrict__ l2w,
                                              float* __restrict__ out) {
    __shared__ float red[16];
    __shared__ int s_last;
    __shared__ float s_c[B_], s_ce[B_];
    int q = blockIdx.x, tid = threadIdx.x;
    int lane = tid & 31, warp = tid >> 5;
    int labq = g_lab[q];
    float den = 0.f, num = 0.f;
    for (int n = tid; n < ROWS; n += 256) {
        float g = 0.f;
#pragma unroll
        for (int s = 0; s < SPLITK; s++) g += g_Gk[s][q * ROWS + n];
        float e = __expf(g * 0.0625f);              // TAU = 16
        e = g_val[n] ? e : 0.f;
        den += e;
        if (g_lab[n] == labq) num += e;
    }
#pragma unroll
    for (int o = 16; o; o >>= 1) {
        den += __shfl_down_sync(0xffffffffu, den, o);
        num += __shfl_down_sync(0xffffffffu, num, o);
    }
    if (lane == 0) { red[warp] = den; red[8 + warp] = num; }
    __syncthreads();
    if (tid == 0) {
        float d = 0.f, nm = 0.f;
#pragma unroll
        for (int w = 0; w < 8; w++) { d += red[w]; nm += red[8 + w]; }
        g_per[q] = g_val[q] ? -__logf(nm / d) : 0.f;
        __threadfence();
        int o = atomicAdd(&g_cnt3, 1);
        s_last = (o == ROWS - 1);
    }
    __syncthreads();

    if (s_last) {                                   // last block: final scalar
        __threadfence();
        if (tid < B_) {
            int b = tid;
            float s = 0.f; int c = 0;
            for (int k = 0; k < KH; k++) { int r = b * KH + k; s += g_per[r]; c += g_val[r]; }
            for (int k = 0; k < KL; k++) { int r = HROWS + b * KL + k; s += g_per[r]; c += g_val[r]; }
            s_c[b] = s / (float)c;
            float se = __expf(ori[b * 2 + 0]) + __expf(ori[b * 2 + 1]);
            s_ce[b] = -__logf(__expf(t_logit[0]) / se);
        }
        __syncthreads();
        if (tid == 0) {
            float contr = 0.f, ce = 0.f;
#pragma unroll
            for (int b = 0; b < B_; b++) { contr += s_c[b]; ce += s_ce[b]; }
            contr /= (float)B_;
            ce /= (float)B_;

            unsigned mx = 0u;
            float sum = 0.f;
#pragma unroll
            for (int i = 0; i < B_; i++) { mx = max(mx, g_pmax[i]); sum += g_psum[i]; }
            float gmax = __uint_as_float(mx);
            float meanv = sum / (float)(B_ * N_);
            float Dm = meanv / gmax;
            float l2 = 0.0001f * (1.f - Dm) * (1.f - Dm) * l2w[0];

            out[0] = contr + ce + l2;
            g_cnt3 = 0;                             // reset for next replay
            __threadfence();
        }
    }
}

// ---------------- launch ----------------
extern "C" void kernel_launch(void* const* d_in, const int* in_sizes, int n_in,
                              void* d_out, int out_size) {
    const float* fea     = (const float*)d_in[0];
    const float* score   = (const float*)d_in[1];
    const int*   label   = (const int*)d_in[2];
    const float* t_logit = (const float*)d_in[3];
    const float* ori     = (const float*)d_in[4];
    const float* l2w     = (const float*)d_in[5];
    float* out = (float*)d_out;

    k_selall<<<32, 256>>>(score, label);
    k_gemm<<<25 * SPLITK, 256>>>(fea);
    k_loss<<<ROWS, 256>>>(t_logit, ori, l2w, out);
}

// round 11
// speedup vs baseline: 1.2952x; 1.0642x over previous
#include <cuda_runtime.h>

#define B_    16
#define N_    2048
#define D_    1024
#define KH    15
#define KL    5
#define ROWS  320      // B_*KH + B_*KL
#define HROWS 240      // B_*KH
#define SPLITK 16
#define KC    (D_ / SPLITK)   // 64

#define BM 64
#define BN 64
#define BK 16
#define SELBLK 32
#define GEMMBLK (25 * SPLITK)       // 400

// ---------------- scratch (no allocations allowed) ----------------
__device__ unsigned int g_pmax[B_];
__device__ float        g_psum[B_];
__device__ int          g_idx[ROWS];
__device__ int          g_val[ROWS];
__device__ int          g_lab[ROWS];
__device__ __align__(16) float g_Gk[SPLITK][ROWS * ROWS];
__device__ float        g_per[ROWS];
__device__ int          g_seldone;  // selection-ready counter (reset by k_loss)
__device__ int          g_cnt3;     // completion counter in k_loss

// ---------------- helpers ----------------
__device__ __forceinline__ unsigned long long u64min(unsigned long long a,
                                                     unsigned long long b) {
    return a < b ? a : b;
}

// warp-wide 64-bit min via two u32 REDUX ops (every lane gets the result)
__device__ __forceinline__ unsigned long long warpmin64(unsigned long long v) {
    unsigned hi = (unsigned)(v >> 32);
    unsigned lo = (unsigned)v;
    unsigned mh = __reduce_min_sync(0xffffffffu, hi);
    unsigned lsel = (hi == mh) ? lo : 0xffffffffu;
    unsigned ml = __reduce_min_sync(0xffffffffu, lsel);
    return ((unsigned long long)mh << 32) | ml;
}

__device__ __forceinline__ unsigned long long f32x2_fma(unsigned long long c,
                                                        unsigned long long a,
                                                        unsigned long long b) {
    asm("fma.rn.f32x2 %0, %1, %2, %0;" : "+l"(c) : "l"(a), "l"(b));
    return c;
}

__device__ __forceinline__ unsigned long long dup_f32(float x) {
    unsigned long long r;
    unsigned u = __float_as_uint(x);
    asm("mov.b64 %0, {%1, %1};" : "=l"(r) : "r"(u));
    return r;
}

__device__ __forceinline__ int ld_cg(const int* p) {
    int v;
    asm volatile("ld.global.cg.b32 %0, [%1];" : "=r"(v) : "l"(p));
    return v;
}

// ===== K1: selection (blocks 0-31) + gram GEMM (blocks 32-431), one kernel ===
// Selection: blocks 0-15 HIGH top-15 of bag bid; blocks 16-31 LOW of bag bid-16.
// Every selection block computes the global score bound itself by streaming
// all B_*N_ scores, so selection needs NO cross-block communication; gemm
// blocks spin on g_seldone (they would otherwise idle during selection).
// key = (score_bits << 32) | idx -> lexicographic (score, idx), matching
// jnp stable ascending argsort (score >= 0). Only the selected SET (and the
// even ranks for LOW) matters: order within a bag is loss-invariant.
__global__ void __launch_bounds__(256, 3)
k_selgemm(const float* __restrict__ fea, const float* __restrict__ score,
          const int* __restrict__ label) {
    __shared__ __align__(16) float As[2][BK][BM + 4];
    __shared__ __align__(16) float Bs[2][BK][BN + 4];
    __shared__ unsigned long long s_cand[128];
    __shared__ unsigned s_r[8];
    __shared__ float    s_bsum[8];
    __shared__ unsigned s_bmax[8];
    int bid = blockIdx.x, tid = threadIdx.x;
    int lane = tid & 31, warp = tid >> 5;

    if (bid < SELBLK) {
        // ================== selection ==================
        bool isHigh = bid < B_;
        int b = isHigh ? bid : bid - B_;

        // stream ALL scores -> global bound (max for HIGH, min for LOW)
        const float4* s4 = (const float4*)score;
        unsigned gb = isHigh ? 0u : 0xFFFFFFFFu;    // score >= 0 -> bits monotonic
#pragma unroll 16
        for (int i = 0; i < (B_ * N_ / 4) / 256; i++) {  // 32 float4 / thread
            float4 v = s4[tid + i * 256];
            unsigned b0 = __float_as_uint(v.x), b1 = __float_as_uint(v.y);
            unsigned b2 = __float_as_uint(v.z), b3 = __float_as_uint(v.w);
            if (isHigh) gb = max(max(gb, b0), max(b1, max(b2, b3)));
            else        gb = min(min(gb, b0), min(b1, min(b2, b3)));
        }
        gb = isHigh ? __reduce_max_sync(0xffffffffu, gb)
                    : __reduce_min_sync(0xffffffffu, gb);
        if (lane == 0) s_r[warp] = gb;

        // own-bag scalar loads for extraction
        float sc[8];
#pragma unroll
        for (int i = 0; i < 8; i++) sc[i] = score[b * N_ + tid + i * 256];
        if (tid < 128) s_cand[tid] = ~0ULL;

        // bag partials for the final L2 term (HIGH blocks only)
        if (isHigh) {
            float s = 0.f;
            unsigned mx = 0u;
#pragma unroll
            for (int i = 0; i < 8; i++) {
                s += sc[i];
                mx = max(mx, __float_as_uint(sc[i]));
            }
#pragma unroll
            for (int o = 16; o; o >>= 1)
                s += __shfl_down_sync(0xffffffffu, s, o);
            mx = __reduce_max_sync(0xffffffffu, mx);
            if (lane == 0) { s_bsum[warp] = s; s_bmax[warp] = mx; }
        }
        __syncthreads();

        unsigned gbound = isHigh ? 0u : 0xFFFFFFFFu;
#pragma unroll
        for (int w = 0; w < 8; w++)
            gbound = isHigh ? max(gbound, s_r[w]) : min(gbound, s_r[w]);

        if (isHigh && tid == 0) {
            float s = 0.f;
            unsigned mx = 0u;
#pragma unroll
            for (int w = 0; w < 8; w++) { s += s_bsum[w]; mx = max(mx, s_bmax[w]); }
            g_psum[b] = s;
            g_pmax[b] = mx;
        }

        float lo, hi;
        if (isHigh) { hi = __uint_as_float(gbound); lo = hi - 0.3f; }
        else        { lo = __uint_as_float(gbound); hi = lo + 1e-9f; }

        unsigned long long key[8];
#pragma unroll
        for (int i = 0; i < 8; i++) {
            key[i] = (sc[i] >= lo && sc[i] <= hi)
                ? (((unsigned long long)__float_as_uint(sc[i]) << 32) |
                   (unsigned)(tid + i * 256))
                : ~0ULL;
        }

        int nl = isHigh ? KH : 10;

        // phase 1: each warp extracts its local top-nl
        {
            unsigned long long loc = key[0];
#pragma unroll
            for (int i = 1; i < 8; i++) loc = u64min(loc, key[i]);
            for (int t = 0; t < nl; t++) {
                unsigned long long m = warpmin64(loc);
                if (m == ~0ULL) break;                // warp exhausted
                if (lane == 0) s_cand[warp * nl + t] = m;
                if (loc == m) {                       // unique owner pops
#pragma unroll
                    for (int i = 0; i < 8; i++) if (key[i] == m) key[i] = ~0ULL;
                    loc = key[0];
#pragma unroll
                    for (int i = 1; i < 8; i++) loc = u64min(loc, key[i]);
                }
            }
        }
        __syncthreads();

        // phase 2: warp 0 merges the 8*nl candidates
        if (warp == 0) {
            unsigned long long cand[4];
#pragma unroll
            for (int j = 0; j < 4; j++) cand[j] = s_cand[lane + 32 * j];
            unsigned long long loc = u64min(u64min(cand[0], cand[1]),
                                            u64min(cand[2], cand[3]));
            int labb = isHigh ? label[b] : 2;
            unsigned long long myv = ~0ULL;           // lane t's winner
            int tend = nl;
            for (int t = 0; t < nl; t++) {
                unsigned long long m = warpmin64(loc);
                if (m == ~0ULL) { tend = t; break; }
                if (lane == t) myv = m;
                if (loc == m) {
#pragma unroll
                    for (int j = 0; j < 4; j++) if (cand[j] == m) cand[j] = ~0ULL;
                    loc = u64min(u64min(cand[0], cand[1]),
                                 u64min(cand[2], cand[3]));
                }
            }
            if (isHigh) {
                if (lane < KH) {
                    int r = b * KH + lane;
                    if (lane < tend) {
                        g_val[r] = 1;
                        g_idx[r] = b * N_ + (int)(myv & 0xFFFFFFFFULL);
                    } else { g_val[r] = 0; g_idx[r] = 0; }
                    g_lab[r] = labb;
                }
            } else {
                // keep even ranks 0,2,4,6,8 -> slot j gets rank 2j
                unsigned long long ev = __shfl_sync(0xffffffffu, myv,
                                                    (lane < KL) ? 2 * lane : 0);
                if (lane < KL) {
                    int r = HROWS + b * KL + lane;
                    if (2 * lane < tend) {
                        g_val[r] = 1;
                        g_idx[r] = b * N_ + (int)(ev & 0xFFFFFFFFULL);
                    } else { g_val[r] = 0; g_idx[r] = 0; }
                    g_lab[r] = 2;  // N_CLASSES
                }
            }
        }

        // signal: this bag's selection results are globally visible
        __syncthreads();
        if (tid == 0) {
            __threadfence();
            atomicAdd(&g_seldone, 1);
        }
        return;
    }

    // ================== gram GEMM (blocks 32..431) ==================
    // wait for all 32 selection blocks (they run concurrently; co-residency
    // is guaranteed: 432 blocks <= 148 SMs * 3 via __launch_bounds__)
    if (tid == 0) {
        while (ld_cg(&g_seldone) < SELBLK) { __nanosleep(32); }
        __threadfence();
    }
    __syncthreads();

    int gb = bid - SELBLK;                     // 0..399
    int kz = gb & (SPLITK - 1), tile = gb / SPLITK;
    int bm = tile / 5, bn = tile % 5;
    int tx = tid & 15, ty = tid >> 4;
    int tx4 = tx * 4, ty4 = ty * 4;

    unsigned long long cc[4][2];
#pragma unroll
    for (int i = 0; i < 4; i++) { cc[i][0] = 0ULL; cc[i][1] = 0ULL; }

    int loadRow = tid >> 2;           // 0..63
    int loadK4  = (tid & 3) * 4;      // 0,4,8,12
    // indirect gather: invalid rows point at row 0; masked in k_loss
    const float* A0 = fea + (size_t)g_idx[bm * BM + loadRow] * D_ + kz * KC + loadK4;
    const float* B0 = fea + (size_t)g_idx[bn * BN + loadRow] * D_ + kz * KC + loadK4;

    float4 a = *(const float4*)A0;
    float4 b4 = *(const float4*)B0;
    As[0][loadK4 + 0][loadRow] = a.x;
    As[0][loadK4 + 1][loadRow] = a.y;
    As[0][loadK4 + 2][loadRow] = a.z;
    As[0][loadK4 + 3][loadRow] = a.w;
    Bs[0][loadK4 + 0][loadRow] = b4.x;
    Bs[0][loadK4 + 1][loadRow] = b4.y;
    Bs[0][loadK4 + 2][loadRow] = b4.z;
    Bs[0][loadK4 + 3][loadRow] = b4.w;
    __syncthreads();

#pragma unroll
    for (int it = 0; it < KC / BK; it++) {
        int cur = it & 1;
        if (it < KC / BK - 1) {                      // prefetch next slab
            a  = *(const float4*)(A0 + (it + 1) * BK);
            b4 = *(const float4*)(B0 + (it + 1) * BK);
        }
#pragma unroll
        for (int k = 0; k < BK; k++) {
            float4 av = *(const float4*)&As[cur][k][ty4];    // LDS.128
            float4 bv = *(const float4*)&Bs[cur][k][tx4];    // LDS.128
            unsigned long long bp0, bp1;
            asm("mov.b64 %0, {%1, %2};" : "=l"(bp0)
                : "r"(__float_as_uint(bv.x)), "r"(__float_as_uint(bv.y)));
            asm("mov.b64 %0, {%1, %2};" : "=l"(bp1)
                : "r"(__float_as_uint(bv.z)), "r"(__float_as_uint(bv.w)));
            unsigned long long A0d = dup_f32(av.x);
            unsigned long long A1d = dup_f32(av.y);
            unsigned long long A2d = dup_f32(av.z);
            unsigned long long A3d = dup_f32(av.w);
            cc[0][0] = f32x2_fma(cc[0][0], A0d, bp0);
            cc[0][1] = f32x2_fma(cc[0][1], A0d, bp1);
            cc[1][0] = f32x2_fma(cc[1][0], A1d, bp0);
            cc[1][1] = f32x2_fma(cc[1][1], A1d, bp1);
            cc[2][0] = f32x2_fma(cc[2][0], A2d, bp0);
            cc[2][1] = f32x2_fma(cc[2][1], A2d, bp1);
            cc[3][0] = f32x2_fma(cc[3][0], A3d, bp0);
            cc[3][1] = f32x2_fma(cc[3][1], A3d, bp1);
        }
        if (it < KC / BK - 1) {
            int nxt = cur ^ 1;
            As[nxt][loadK4 + 0][loadRow] = a.x;
            As[nxt][loadK4 + 1][loadRow] = a.y;
            As[nxt][loadK4 + 2][loadRow] = a.z;
            As[nxt][loadK4 + 3][loadRow] = a.w;
            Bs[nxt][loadK4 + 0][loadRow] = b4.x;
            Bs[nxt][loadK4 + 1][loadRow] = b4.y;
            Bs[nxt][loadK4 + 2][loadRow] = b4.z;
            Bs[nxt][loadK4 + 3][loadRow] = b4.w;
            __syncthreads();
        }
    }

    float* og = g_Gk[kz];
#pragma unroll
    for (int i = 0; i < 4; i++) {
        unsigned lo0, hi0, lo1, hi1;
        asm("mov.b64 {%0, %1}, %2;" : "=r"(lo0), "=r"(hi0) : "l"(cc[i][0]));
        asm("mov.b64 {%0, %1}, %2;" : "=r"(lo1), "=r"(hi1) : "l"(cc[i][1]));
        float4 v = make_float4(__uint_as_float(lo0), __uint_as_float(hi0),
                               __uint_as_float(lo1), __uint_as_float(hi1));
        int row = bm * BM + ty4 + i;
        *(float4*)(og + (size_t)row * ROWS + bn * BN + tx4) = v;
    }
}

// ===== K2: per-query loss (320 blocks) + fused final scalar ==================
__global__ void __launch_bounds__(256) k_loss(const float* __restrict__ t_logit,
                                              const float* __restrict__ ori,
                                              const float* __restrict__ l2w,
                                              float* __restrict__ out) {
    __shared__ float red[16];
    __shared__ int s_last;
    __shared__ float s_c[B_], s_ce[B_];
    int q = blockIdx.x, tid = threadIdx.x;
    int lane = tid & 31, warp = tid >> 5;
    int labq = g_lab[q];
    float den = 0.f, num = 0.f;
    for (int n = tid; n < ROWS; n += 256) {
        float g = 0.f;
#pragma unroll
        for (int s = 0; s < SPLITK; s++) g += g_Gk[s][q * ROWS + n];
        float e = __expf(g * 0.0625f);              // TAU = 16
        e = g_val[n] ? e : 0.f;
        den += e;
        if (g_lab[n] == labq) num += e;
    }
#pragma unroll
    for (int o = 16; o; o >>= 1) {
        den += __shfl_down_sync(0xffffffffu, den, o);
        num += __shfl_down_sync(0xffffffffu, num, o);
    }
    if (lane == 0) { red[warp] = den; red[8 + warp] = num; }
    __syncthreads();
    if (tid == 0) {
        float d = 0.f, nm = 0.f;
#pragma unroll
        for (int w = 0; w < 8; w++) { d += red[w]; nm += red[8 + w]; }
        g_per[q] = g_val[q] ? -__logf(nm / d) : 0.f;
        __threadfence();
        int o = atomicAdd(&g_cnt3, 1);
        s_last = (o == ROWS - 1);
    }
    __syncthreads();

    if (s_last) {                                   // last block: final scalar
        __threadfence();
        if (tid < B_) {
            int b = tid;
            float s = 0.f; int c = 0;
            for (int k = 0; k < KH; k++) { int r = b * KH + k; s += g_per[r]; c += g_val[r]; }
            for (int k = 0; k < KL; k++) { int r = HROWS + b * KL + k; s += g_per[r]; c += g_val[r]; }
            s_c[b] = s / (float)c;
            float se = __expf(ori[b * 2 + 0]) + __expf(ori[b * 2 + 1]);
            s_ce[b] = -__logf(__expf(t_logit[0]) / se);
        }
        __syncthreads();
        if (tid == 0) {
            float contr = 0.f, ce = 0.f;
#pragma unroll
            for (int b = 0; b < B_; b++) { contr += s_c[b]; ce += s_ce[b]; }
            contr /= (float)B_;
            ce /= (float)B_;

            unsigned mx = 0u;
            float sum = 0.f;
#pragma unroll
            for (int i = 0; i < B_; i++) { mx = max(mx, g_pmax[i]); sum += g_psum[i]; }
            float gmax = __uint_as_float(mx);
            float meanv = sum / (float)(B_ * N_);
            float Dm = meanv / gmax;
            float l2 = 0.0001f * (1.f - Dm) * (1.f - Dm) * l2w[0];

            out[0] = contr + ce + l2;
            g_cnt3 = 0;                             // reset for next replay
            g_seldone = 0;                          // reset k_selgemm's flag
            __threadfence();
        }
    }
}

// ---------------- launch ----------------
extern "C" void kernel_launch(void* const* d_in, const int* in_sizes, int n_in,
                              void* d_out, int out_size) {
    const float* fea     = (const float*)d_in[0];
    const float* score   = (const float*)d_in[1];
    const int*   label   = (const int*)d_in[2];
    const float* t_logit = (const float*)d_in[3];
    const float* ori     = (const float*)d_in[4];
    const float* l2w     = (const float*)d_in[5];
    float* out = (float*)d_out;

    k_selgemm<<<SELBLK + GEMMBLK, 256>>>(fea, score, label);
    k_loss<<<ROWS, 256>>>(t_logit, ori, l2w, out);
}

// round 12
// speedup vs baseline: 1.2982x; 1.0023x over previous
#include <cuda_runtime.h>

#define B_    16
#define N_    2048
#define D_    1024
#define KH    15
#define KL    5
#define ROWS  320      // B_*KH + B_*KL
#define HROWS 240      // B_*KH
#define SPLITK 16
#define KC    (D_ / SPLITK)   // 64

#define BM 64
#define BN 64
#define BK 16
#define SELBLK 32
#define GEMMBLK (25 * SPLITK)             // 400
#define GRID_ (SELBLK + GEMMBLK)          // 432

// ---------------- scratch (no allocations allowed) ----------------
__device__ unsigned int g_pmax[B_];
__device__ float        g_psum[B_];
__device__ int          g_idx[ROWS];
__device__ int          g_val[ROWS];
__device__ int          g_lab[ROWS];
__device__ __align__(16) float g_Gk[SPLITK][ROWS * ROWS];
__device__ float        g_per[ROWS];
__device__ int          g_seldone;  // selection-ready counter
__device__ int          g_bar;      // gemm->loss grid barrier
__device__ int          g_cnt;      // completion counter (counts ALL blocks)

// ---------------- helpers ----------------
__device__ __forceinline__ unsigned long long u64min(unsigned long long a,
                                                     unsigned long long b) {
    return a < b ? a : b;
}

// warp-wide 64-bit min via two u32 REDUX ops (every lane gets the result)
__device__ __forceinline__ unsigned long long warpmin64(unsigned long long v) {
    unsigned hi = (unsigned)(v >> 32);
    unsigned lo = (unsigned)v;
    unsigned mh = __reduce_min_sync(0xffffffffu, hi);
    unsigned lsel = (hi == mh) ? lo : 0xffffffffu;
    unsigned ml = __reduce_min_sync(0xffffffffu, lsel);
    return ((unsigned long long)mh << 32) | ml;
}

__device__ __forceinline__ unsigned long long f32x2_fma(unsigned long long c,
                                                        unsigned long long a,
                                                        unsigned long long b) {
    asm("fma.rn.f32x2 %0, %1, %2, %0;" : "+l"(c) : "l"(a), "l"(b));
    return c;
}

__device__ __forceinline__ unsigned long long dup_f32(float x) {
    unsigned long long r;
    unsigned u = __float_as_uint(x);
    asm("mov.b64 %0, {%1, %1};" : "=l"(r) : "r"(u));
    return r;
}

__device__ __forceinline__ int ld_cg(const int* p) {
    int v;
    asm volatile("ld.global.cg.b32 %0, [%1];" : "=r"(v) : "l"(p));
    return v;
}

// ===== ONE kernel: selection (0-31) | gemm (32-431) | barrier | loss (0-319) =
// Selection: blocks 0-15 HIGH top-15 of bag bid; blocks 16-31 LOW of bag bid-16.
// Every selection block computes the global score bound itself by streaming
// all B_*N_ scores -> NO cross-block communication inside selection; gemm
// blocks spin on g_seldone. After the gemm a single grid barrier releases the
// loss phase (one query per block). The globally-last block (counter over all
// GRID_ blocks) computes the final scalar and resets state for graph replay.
// key = (score_bits << 32) | idx -> lexicographic (score, idx), matching
// jnp stable ascending argsort (score >= 0). Only the selected SET (and the
// even ranks for LOW) matters: order within a bag is loss-invariant.
__global__ void __launch_bounds__(256, 3)
k_all(const float* __restrict__ fea, const float* __restrict__ score,
      const int* __restrict__ label, const float* __restrict__ t_logit,
      const float* __restrict__ ori, const float* __restrict__ l2w,
      float* __restrict__ out) {
    __shared__ __align__(16) float As[2][BK][BM + 4];
    __shared__ __align__(16) float Bs[2][BK][BN + 4];
    __shared__ unsigned long long s_cand[128];
    __shared__ unsigned s_r[8];
    __shared__ float    s_bsum[8];
    __shared__ unsigned s_bmax[8];
    __shared__ float    red[16];
    __shared__ int      s_last;
    __shared__ float    s_c[B_], s_ce[B_];
    int bid = blockIdx.x, tid = threadIdx.x;
    int lane = tid & 31, warp = tid >> 5;

    if (bid < SELBLK) {
        // ================== selection ==================
        bool isHigh = bid < B_;
        int b = isHigh ? bid : bid - B_;

        // stream ALL scores -> global bound (max for HIGH, min for LOW)
        const float4* s4 = (const float4*)score;
        unsigned gbv = isHigh ? 0u : 0xFFFFFFFFu;   // score >= 0 -> bits monotonic
#pragma unroll 16
        for (int i = 0; i < (B_ * N_ / 4) / 256; i++) {  // 32 float4 / thread
            float4 v = s4[tid + i * 256];
            unsigned b0 = __float_as_uint(v.x), b1 = __float_as_uint(v.y);
            unsigned b2 = __float_as_uint(v.z), b3 = __float_as_uint(v.w);
            if (isHigh) gbv = max(max(gbv, b0), max(b1, max(b2, b3)));
            else        gbv = min(min(gbv, b0), min(b1, min(b2, b3)));
        }
        gbv = isHigh ? __reduce_max_sync(0xffffffffu, gbv)
                     : __reduce_min_sync(0xffffffffu, gbv);
        if (lane == 0) s_r[warp] = gbv;

        // own-bag scalar loads for extraction
        float sc[8];
#pragma unroll
        for (int i = 0; i < 8; i++) sc[i] = score[b * N_ + tid + i * 256];
        if (tid < 128) s_cand[tid] = ~0ULL;

        // bag partials for the final L2 term (HIGH blocks only)
        if (isHigh) {
            float s = 0.f;
            unsigned mx = 0u;
#pragma unroll
            for (int i = 0; i < 8; i++) {
                s += sc[i];
                mx = max(mx, __float_as_uint(sc[i]));
            }
#pragma unroll
            for (int o = 16; o; o >>= 1)
                s += __shfl_down_sync(0xffffffffu, s, o);
            mx = __reduce_max_sync(0xffffffffu, mx);
            if (lane == 0) { s_bsum[warp] = s; s_bmax[warp] = mx; }
        }
        __syncthreads();

        unsigned gbound = isHigh ? 0u : 0xFFFFFFFFu;
#pragma unroll
        for (int w = 0; w < 8; w++)
            gbound = isHigh ? max(gbound, s_r[w]) : min(gbound, s_r[w]);

        if (isHigh && tid == 0) {
            float s = 0.f;
            unsigned mx = 0u;
#pragma unroll
            for (int w = 0; w < 8; w++) { s += s_bsum[w]; mx = max(mx, s_bmax[w]); }
            g_psum[b] = s;
            g_pmax[b] = mx;
        }

        float lo, hi;
        if (isHigh) { hi = __uint_as_float(gbound); lo = hi - 0.3f; }
        else        { lo = __uint_as_float(gbound); hi = lo + 1e-9f; }

        unsigned long long key[8];
#pragma unroll
        for (int i = 0; i < 8; i++) {
            key[i] = (sc[i] >= lo && sc[i] <= hi)
                ? (((unsigned long long)__float_as_uint(sc[i]) << 32) |
                   (unsigned)(tid + i * 256))
                : ~0ULL;
        }

        int nl = isHigh ? KH : 10;

        // phase 1: each warp extracts its local top-nl
        {
            unsigned long long loc = key[0];
#pragma unroll
            for (int i = 1; i < 8; i++) loc = u64min(loc, key[i]);
            for (int t = 0; t < nl; t++) {
                unsigned long long m = warpmin64(loc);
                if (m == ~0ULL) break;                // warp exhausted
                if (lane == 0) s_cand[warp * nl + t] = m;
                if (loc == m) {                       // unique owner pops
#pragma unroll
                    for (int i = 0; i < 8; i++) if (key[i] == m) key[i] = ~0ULL;
                    loc = key[0];
#pragma unroll
                    for (int i = 1; i < 8; i++) loc = u64min(loc, key[i]);
                }
            }
        }
        __syncthreads();

        // phase 2: warp 0 merges the 8*nl candidates
        if (warp == 0) {
            unsigned long long cand[4];
#pragma unroll
            for (int j = 0; j < 4; j++) cand[j] = s_cand[lane + 32 * j];
            unsigned long long loc = u64min(u64min(cand[0], cand[1]),
                                            u64min(cand[2], cand[3]));
            int labb = isHigh ? label[b] : 2;
            unsigned long long myv = ~0ULL;           // lane t's winner
            int tend = nl;
            for (int t = 0; t < nl; t++) {
                unsigned long long m = warpmin64(loc);
                if (m == ~0ULL) { tend = t; break; }
                if (lane == t) myv = m;
                if (loc == m) {
#pragma unroll
                    for (int j = 0; j < 4; j++) if (cand[j] == m) cand[j] = ~0ULL;
                    loc = u64min(u64min(cand[0], cand[1]),
                                 u64min(cand[2], cand[3]));
                }
            }
            if (isHigh) {
                if (lane < KH) {
                    int r = b * KH + lane;
                    if (lane < tend) {
                        g_val[r] = 1;
                        g_idx[r] = b * N_ + (int)(myv & 0xFFFFFFFFULL);
                    } else { g_val[r] = 0; g_idx[r] = 0; }
                    g_lab[r] = labb;
                }
            } else {
                // keep even ranks 0,2,4,6,8 -> slot j gets rank 2j
                unsigned long long ev = __shfl_sync(0xffffffffu, myv,
                                                    (lane < KL) ? 2 * lane : 0);
                if (lane < KL) {
                    int r = HROWS + b * KL + lane;
                    if (2 * lane < tend) {
                        g_val[r] = 1;
                        g_idx[r] = b * N_ + (int)(ev & 0xFFFFFFFFULL);
                    } else { g_val[r] = 0; g_idx[r] = 0; }
                    g_lab[r] = 2;  // N_CLASSES
                }
            }
        }

        // signal: this bag's selection results are globally visible
        __syncthreads();
        if (tid == 0) {
            __threadfence();
            atomicAdd(&g_seldone, 1);
        }
    } else {
        // ================== gram GEMM (blocks 32..431) ==================
        if (tid == 0) {
            while (ld_cg(&g_seldone) < SELBLK) { __nanosleep(32); }
            __threadfence();
        }
        __syncthreads();

        int gb = bid - SELBLK;                 // 0..399
        int kz = gb & (SPLITK - 1), tile = gb / SPLITK;
        int bm = tile / 5, bn = tile % 5;
        int tx = tid & 15, ty = tid >> 4;
        int tx4 = tx * 4, ty4 = ty * 4;

        unsigned long long cc[4][2];
#pragma unroll
        for (int i = 0; i < 4; i++) { cc[i][0] = 0ULL; cc[i][1] = 0ULL; }

        int loadRow = tid >> 2;           // 0..63
        int loadK4  = (tid & 3) * 4;      // 0,4,8,12
        // indirect gather: invalid rows point at row 0; masked in loss phase
        const float* A0 = fea + (size_t)g_idx[bm * BM + loadRow] * D_ + kz * KC + loadK4;
        const float* B0 = fea + (size_t)g_idx[bn * BN + loadRow] * D_ + kz * KC + loadK4;

        float4 a = *(const float4*)A0;
        float4 b4 = *(const float4*)B0;
        As[0][loadK4 + 0][loadRow] = a.x;
        As[0][loadK4 + 1][loadRow] = a.y;
        As[0][loadK4 + 2][loadRow] = a.z;
        As[0][loadK4 + 3][loadRow] = a.w;
        Bs[0][loadK4 + 0][loadRow] = b4.x;
        Bs[0][loadK4 + 1][loadRow] = b4.y;
        Bs[0][loadK4 + 2][loadRow] = b4.z;
        Bs[0][loadK4 + 3][loadRow] = b4.w;
        __syncthreads();

#pragma unroll
        for (int it = 0; it < KC / BK; it++) {
            int cur = it & 1;
            if (it < KC / BK - 1) {                  // prefetch next slab
                a  = *(const float4*)(A0 + (it + 1) * BK);
                b4 = *(const float4*)(B0 + (it + 1) * BK);
            }
#pragma unroll
            for (int k = 0; k < BK; k++) {
                float4 av = *(const float4*)&As[cur][k][ty4];    // LDS.128
                float4 bv = *(const float4*)&Bs[cur][k][tx4];    // LDS.128
                unsigned long long bp0, bp1;
                asm("mov.b64 %0, {%1, %2};" : "=l"(bp0)
                    : "r"(__float_as_uint(bv.x)), "r"(__float_as_uint(bv.y)));
                asm("mov.b64 %0, {%1, %2};" : "=l"(bp1)
                    : "r"(__float_as_uint(bv.z)), "r"(__float_as_uint(bv.w)));
                unsigned long long A0d = dup_f32(av.x);
                unsigned long long A1d = dup_f32(av.y);
                unsigned long long A2d = dup_f32(av.z);
                unsigned long long A3d = dup_f32(av.w);
                cc[0][0] = f32x2_fma(cc[0][0], A0d, bp0);
                cc[0][1] = f32x2_fma(cc[0][1], A0d, bp1);
                cc[1][0] = f32x2_fma(cc[1][0], A1d, bp0);
                cc[1][1] = f32x2_fma(cc[1][1], A1d, bp1);
                cc[2][0] = f32x2_fma(cc[2][0], A2d, bp0);
                cc[2][1] = f32x2_fma(cc[2][1], A2d, bp1);
                cc[3][0] = f32x2_fma(cc[3][0], A3d, bp0);
                cc[3][1] = f32x2_fma(cc[3][1], A3d, bp1);
            }
            if (it < KC / BK - 1) {
                int nxt = cur ^ 1;
                As[nxt][loadK4 + 0][loadRow] = a.x;
                As[nxt][loadK4 + 1][loadRow] = a.y;
                As[nxt][loadK4 + 2][loadRow] = a.z;
                As[nxt][loadK4 + 3][loadRow] = a.w;
                Bs[nxt][loadK4 + 0][loadRow] = b4.x;
                Bs[nxt][loadK4 + 1][loadRow] = b4.y;
                Bs[nxt][loadK4 + 2][loadRow] = b4.z;
                Bs[nxt][loadK4 + 3][loadRow] = b4.w;
                __syncthreads();
            }
        }

        float* og = g_Gk[kz];
#pragma unroll
        for (int i = 0; i < 4; i++) {
            unsigned lo0, hi0, lo1, hi1;
            asm("mov.b64 {%0, %1}, %2;" : "=r"(lo0), "=r"(hi0) : "l"(cc[i][0]));
            asm("mov.b64 {%0, %1}, %2;" : "=r"(lo1), "=r"(hi1) : "l"(cc[i][1]));
            float4 v = make_float4(__uint_as_float(lo0), __uint_as_float(hi0),
                                   __uint_as_float(lo1), __uint_as_float(hi1));
            int row = bm * BM + ty4 + i;
            *(float4*)(og + (size_t)row * ROWS + bn * BN + tx4) = v;
        }
    }

    // ================== grid barrier over all GRID_ blocks ==================
    __syncthreads();
    if (tid == 0) {
        __threadfence();
        atomicAdd(&g_bar, 1);
        while (ld_cg(&g_bar) < GRID_) { __nanosleep(32); }
        __threadfence();
    }
    __syncthreads();

    // ================== loss phase (blocks 0-319, one query each) ==========
    if (bid < ROWS) {
        int q = bid;
        int labq = g_lab[q];
        float den = 0.f, num = 0.f;
        for (int n = tid; n < ROWS; n += 256) {
            float g = 0.f;
#pragma unroll
            for (int s = 0; s < SPLITK; s++) g += g_Gk[s][q * ROWS + n];
            float e = __expf(g * 0.0625f);          // TAU = 16
            e = g_val[n] ? e : 0.f;
            den += e;
            if (g_lab[n] == labq) num += e;
        }
#pragma unroll
        for (int o = 16; o; o >>= 1) {
            den += __shfl_down_sync(0xffffffffu, den, o);
            num += __shfl_down_sync(0xffffffffu, num, o);
        }
        if (lane == 0) { red[warp] = den; red[8 + warp] = num; }
        __syncthreads();
        if (tid == 0) {
            float d = 0.f, nm = 0.f;
#pragma unroll
            for (int w = 0; w < 8; w++) { d += red[w]; nm += red[8 + w]; }
            g_per[q] = g_val[q] ? -__logf(nm / d) : 0.f;
        }
    }

    // ================== completion counter over ALL blocks =================
    __syncthreads();
    if (tid == 0) {
        __threadfence();
        int o = atomicAdd(&g_cnt, 1);
        s_last = (o == GRID_ - 1);     // globally last -> all g_per visible
    }
    __syncthreads();

    if (s_last) {
        __threadfence();
        if (tid < B_) {
            int b = tid;
            float s = 0.f; int c = 0;
            for (int k = 0; k < KH; k++) { int r = b * KH + k; s += g_per[r]; c += g_val[r]; }
            for (int k = 0; k < KL; k++) { int r = HROWS + b * KL + k; s += g_per[r]; c += g_val[r]; }
            s_c[b] = s / (float)c;
            float se = __expf(ori[b * 2 + 0]) + __expf(ori[b * 2 + 1]);
            s_ce[b] = -__logf(__expf(t_logit[0]) / se);
        }
        __syncthreads();
        if (tid == 0) {
            float contr = 0.f, ce = 0.f;
#pragma unroll
            for (int b = 0; b < B_; b++) { contr += s_c[b]; ce += s_ce[b]; }
            contr /= (float)B_;
            ce /= (float)B_;

            unsigned mx = 0u;
            float sum = 0.f;
#pragma unroll
            for (int i = 0; i < B_; i++) { mx = max(mx, g_pmax[i]); sum += g_psum[i]; }
            float gmax = __uint_as_float(mx);
            float meanv = sum / (float)(B_ * N_);
            float Dm = meanv / gmax;
            float l2 = 0.0001f * (1.f - Dm) * (1.f - Dm) * l2w[0];

            out[0] = contr + ce + l2;
            // everyone has passed g_bar (arriving at g_cnt implies it) and
            // g_seldone (gemm blocks passed it before the barrier) -> safe:
            g_seldone = 0;
            g_bar = 0;
            g_cnt = 0;
            __threadfence();
        }
    }
}

// ---------------- launch ----------------
extern "C" void kernel_launch(void* const* d_in, const int* in_sizes, int n_in,
                              void* d_out, int out_size) {
    const float* fea     = (const float*)d_in[0];
    const float* score   = (const float*)d_in[1];
    const int*   label   = (const int*)d_in[2];
    const float* t_logit = (const float*)d_in[3];
    const float* ori     = (const float*)d_in[4];
    const float* l2w     = (const float*)d_in[5];
    float* out = (float*)d_out;

    k_all<<<GRID_, 256>>>(fea, score, label, t_logit, ori, l2w, out);
}

// round 13
// speedup vs baseline: 1.5438x; 1.1892x over previous
#include <cuda_runtime.h>

#define B_    16
#define N_    2048
#define D_    1024
#define KH    15
#define KL    5
#define ROWS  320      // B_*KH + B_*KL
#define HROWS 240      // B_*KH
#define SPLITK 16
#define KC    (D_ / SPLITK)   // 64

#define BM 64
#define BN 64
#define BK 16
#define SELBLK 32
#define GEMMBLK (25 * SPLITK)             // 400
#define GRID_ (SELBLK + GEMMBLK)          // 432
#define LCAP 2048                          // >= bag size: gather can't overflow

// ---------------- scratch (no allocations allowed) ----------------
__device__ unsigned int g_pmax[B_];
__device__ float        g_psum[B_];
__device__ int          g_idx[ROWS];
__device__ int          g_val[ROWS];
__device__ int          g_lab[ROWS];
__device__ __align__(16) float g_Gk[SPLITK][ROWS * ROWS];
__device__ float        g_per[ROWS];
__device__ int          g_seldone;  // selection-ready counter
__device__ int          g_bar;      // gemm->loss grid barrier
__device__ int          g_cnt;      // completion counter (counts ALL blocks)

// ---------------- helpers ----------------
__device__ __forceinline__ unsigned long long f32x2_fma(unsigned long long c,
                                                        unsigned long long a,
                                                        unsigned long long b) {
    asm("fma.rn.f32x2 %0, %1, %2, %0;" : "+l"(c) : "l"(a), "l"(b));
    return c;
}

__device__ __forceinline__ unsigned long long dup_f32(float x) {
    unsigned long long r;
    unsigned u = __float_as_uint(x);
    asm("mov.b64 %0, {%1, %1};" : "=l"(r) : "r"(u));
    return r;
}

__device__ __forceinline__ int ld_cg(const int* p) {
    int v;
    asm volatile("ld.global.cg.b32 %0, [%1];" : "=r"(v) : "l"(p));
    return v;
}

// ===== ONE kernel: selection (0-31) | gemm (32-431) | barrier | loss (0-319) =
// Selection: blocks 0-15 HIGH of bag bid; blocks 16-31 LOW of bag bid-16.
// Each selection block computes the global score bound itself by streaming all
// B_*N_ scores (no cross-block comms). Top-k is found WITHOUT serial
// extraction rounds: gather the candidates in a narrow bottom band of the
// range into smem, then compute each candidate's exact rank by parallel
// counting (keys are unique: (score_bits << 32) | idx). A widening loop
// guarantees the band holds at least min(T, k) candidates; every in-range key
// outside the band is strictly larger than every banded key, so banded ranks
// are exact global ranks. Matches jnp stable ascending argsort (score >= 0).
__global__ void __launch_bounds__(256, 3)
k_all(const float* __restrict__ fea, const float* __restrict__ score,
      const int* __restrict__ label, const float* __restrict__ t_logit,
      const float* __restrict__ ori, const float* __restrict__ l2w,
      float* __restrict__ out) {
    __shared__ __align__(16) float As[2][BK][BM + 4];
    __shared__ __align__(16) float Bs[2][BK][BN + 4];
    __shared__ unsigned long long s_list[LCAP];
    __shared__ unsigned s_r[8];
    __shared__ float    s_bsum[8];
    __shared__ unsigned s_bmax[8];
    __shared__ int      s_red[8];
    __shared__ int      s_cnt;
    __shared__ float    red[16];
    __shared__ int      s_last;
    __shared__ float    s_c[B_], s_ce[B_];
    int bid = blockIdx.x, tid = threadIdx.x;
    int lane = tid & 31, warp = tid >> 5;

    if (bid < SELBLK) {
        // ================== selection ==================
        bool isHigh = bid < B_;
        int b = isHigh ? bid : bid - B_;

        // stream ALL scores -> global bound (max for HIGH, min for LOW)
        const float4* s4 = (const float4*)score;
        unsigned gbv = isHigh ? 0u : 0xFFFFFFFFu;   // score >= 0 -> bits monotonic
#pragma unroll 16
        for (int i = 0; i < (B_ * N_ / 4) / 256; i++) {  // 32 float4 / thread
            float4 v = s4[tid + i * 256];
            unsigned b0 = __float_as_uint(v.x), b1 = __float_as_uint(v.y);
            unsigned b2 = __float_as_uint(v.z), b3 = __float_as_uint(v.w);
            if (isHigh) gbv = max(max(gbv, b0), max(b1, max(b2, b3)));
            else        gbv = min(min(gbv, b0), min(b1, min(b2, b3)));
        }
        gbv = isHigh ? __reduce_max_sync(0xffffffffu, gbv)
                     : __reduce_min_sync(0xffffffffu, gbv);
        if (lane == 0) s_r[warp] = gbv;

        // own-bag scalar loads
        float sc[8];
#pragma unroll
        for (int i = 0; i < 8; i++) sc[i] = score[b * N_ + tid + i * 256];

        // bag partials for the final L2 term (HIGH blocks only)
        if (isHigh) {
            float s = 0.f;
            unsigned mx = 0u;
#pragma unroll
            for (int i = 0; i < 8; i++) {
                s += sc[i];
                mx = max(mx, __float_as_uint(sc[i]));
            }
#pragma unroll
            for (int o = 16; o; o >>= 1)
                s += __shfl_down_sync(0xffffffffu, s, o);
            mx = __reduce_max_sync(0xffffffffu, mx);
            if (lane == 0) { s_bsum[warp] = s; s_bmax[warp] = mx; }
        }
        if (tid == 0) s_cnt = 0;
        __syncthreads();

        unsigned gbound = isHigh ? 0u : 0xFFFFFFFFu;
#pragma unroll
        for (int w = 0; w < 8; w++)
            gbound = isHigh ? max(gbound, s_r[w]) : min(gbound, s_r[w]);

        if (isHigh && tid == 0) {
            float s = 0.f;
            unsigned mx = 0u;
#pragma unroll
            for (int w = 0; w < 8; w++) { s += s_bsum[w]; mx = max(mx, s_bmax[w]); }
            g_psum[b] = s;
            g_pmax[b] = mx;
        }

        float lo, hi;
        if (isHigh) { hi = __uint_as_float(gbound); lo = hi - 0.3f; }
        else        { lo = __uint_as_float(gbound); hi = lo + 1e-9f; }

        // ---- count T = candidates in the FULL range ----
        int myT = 0;
#pragma unroll
        for (int i = 0; i < 8; i++) myT += (sc[i] >= lo && sc[i] <= hi);
        {
            int w = __reduce_add_sync(0xffffffffu, myT);
            if (lane == 0) s_red[warp] = w;
            __syncthreads();
            if (tid == 0) {
                int t = 0;
#pragma unroll
                for (int ww = 0; ww < 8; ww++) t += s_red[ww];
                s_red[0] = t;
            }
            __syncthreads();
        }
        int T = s_red[0];
        int kneed = isHigh ? KH : 10;
        int target = min(T, kneed);

        // ---- band [lo, hi2]: bottom slice holding >= target candidates ----
        float hi2 = hi;
        if (isHigh && T > 0) {
            float delta = 0.3f * 24.f / (float)T;   // expect ~24 in band
            for (;;) {
                hi2 = fminf(hi, lo + delta);
                int mc = 0;
#pragma unroll
                for (int i = 0; i < 8; i++) mc += (sc[i] >= lo && sc[i] <= hi2);
                int w = __reduce_add_sync(0xffffffffu, mc);
                if (lane == 0) s_red[warp] = w;
                __syncthreads();
                if (tid == 0) {
                    int t = 0;
#pragma unroll
                    for (int ww = 0; ww < 8; ww++) t += s_red[ww];
                    s_red[1] = t;
                }
                __syncthreads();
                if (s_red[1] >= target || hi2 >= hi) break;
                delta *= 4.f;
                __syncthreads();
            }
        }

        // ---- gather banded candidates to smem (order arbitrary) ----
#pragma unroll
        for (int i = 0; i < 8; i++) {
            if (sc[i] >= lo && sc[i] <= hi2) {
                int pos = atomicAdd(&s_cnt, 1);
                s_list[pos] =
                    ((unsigned long long)__float_as_uint(sc[i]) << 32) |
                    (unsigned)(tid + i * 256);
            }
        }
        __syncthreads();
        int C = s_cnt;

        // ---- prefill slot metadata (labels + validity for empty slots) ----
        int labb = isHigh ? label[b] : 2;           // 2 = N_CLASSES
        if (isHigh) {
            if (tid < KH) {
                int r = b * KH + tid;
                g_lab[r] = labb;
                if (tid >= target) { g_val[r] = 0; g_idx[r] = 0; }
                else               { g_val[r] = 1; }
            }
        } else {
            int sl = (target + 1) >> 1;             // slots 0..sl-1 valid
            if (tid < KL) {
                int r = HROWS + b * KL + tid;
                g_lab[r] = 2;
                if (tid >= sl) { g_val[r] = 0; g_idx[r] = 0; }
                else           { g_val[r] = 1; }
            }
        }

        // ---- parallel counting-rank: exact rank among in-range candidates --
        for (int i = tid; i < C; i += 256) {
            unsigned long long k = s_list[i];
            int r = 0;
            for (int j = 0; j < C; j++) r += (s_list[j] < k);
            int idx = b * N_ + (int)(k & 0xFFFFFFFFULL);
            if (isHigh) {
                if (r < KH) g_idx[b * KH + r] = idx;
            } else {
                if (r < 10 && !(r & 1)) g_idx[HROWS + b * KL + (r >> 1)] = idx;
            }
        }

        // signal: this bag's selection results are globally visible
        __syncthreads();
        if (tid == 0) {
            __threadfence();
            atomicAdd(&g_seldone, 1);
        }
    } else {
        // ================== gram GEMM (blocks 32..431) ==================
        if (tid == 0) {
            while (ld_cg(&g_seldone) < SELBLK) { __nanosleep(32); }
            __threadfence();
        }
        __syncthreads();

        int gb = bid - SELBLK;                 // 0..399
        int kz = gb & (SPLITK - 1), tile = gb / SPLITK;
        int bm = tile / 5, bn = tile % 5;
        int tx = tid & 15, ty = tid >> 4;
        int tx4 = tx * 4, ty4 = ty * 4;

        unsigned long long cc[4][2];
#pragma unroll
        for (int i = 0; i < 4; i++) { cc[i][0] = 0ULL; cc[i][1] = 0ULL; }

        int loadRow = tid >> 2;           // 0..63
        int loadK4  = (tid & 3) * 4;      // 0,4,8,12
        // indirect gather: invalid rows point at row 0; masked in loss phase
        const float* A0 = fea + (size_t)g_idx[bm * BM + loadRow] * D_ + kz * KC + loadK4;
        const float* B0 = fea + (size_t)g_idx[bn * BN + loadRow] * D_ + kz * KC + loadK4;

        float4 a = *(const float4*)A0;
        float4 b4 = *(const float4*)B0;
        As[0][loadK4 + 0][loadRow] = a.x;
        As[0][loadK4 + 1][loadRow] = a.y;
        As[0][loadK4 + 2][loadRow] = a.z;
        As[0][loadK4 + 3][loadRow] = a.w;
        Bs[0][loadK4 + 0][loadRow] = b4.x;
        Bs[0][loadK4 + 1][loadRow] = b4.y;
        Bs[0][loadK4 + 2][loadRow] = b4.z;
        Bs[0][loadK4 + 3][loadRow] = b4.w;
        __syncthreads();

#pragma unroll
        for (int it = 0; it < KC / BK; it++) {
            int cur = it & 1;
            if (it < KC / BK - 1) {                  // prefetch next slab
                a  = *(const float4*)(A0 + (it + 1) * BK);
                b4 = *(const float4*)(B0 + (it + 1) * BK);
            }
#pragma unroll
            for (int k = 0; k < BK; k++) {
                float4 av = *(const float4*)&As[cur][k][ty4];    // LDS.128
                float4 bv = *(const float4*)&Bs[cur][k][tx4];    // LDS.128
                unsigned long long bp0, bp1;
                asm("mov.b64 %0, {%1, %2};" : "=l"(bp0)
                    : "r"(__float_as_uint(bv.x)), "r"(__float_as_uint(bv.y)));
                asm("mov.b64 %0, {%1, %2};" : "=l"(bp1)
                    : "r"(__float_as_uint(bv.z)), "r"(__float_as_uint(bv.w)));
                unsigned long long A0d = dup_f32(av.x);
                unsigned long long A1d = dup_f32(av.y);
                unsigned long long A2d = dup_f32(av.z);
                unsigned long long A3d = dup_f32(av.w);
                cc[0][0] = f32x2_fma(cc[0][0], A0d, bp0);
                cc[0][1] = f32x2_fma(cc[0][1], A0d, bp1);
                cc[1][0] = f32x2_fma(cc[1][0], A1d, bp0);
                cc[1][1] = f32x2_fma(cc[1][1], A1d, bp1);
                cc[2][0] = f32x2_fma(cc[2][0], A2d, bp0);
                cc[2][1] = f32x2_fma(cc[2][1], A2d, bp1);
                cc[3][0] = f32x2_fma(cc[3][0], A3d, bp0);
                cc[3][1] = f32x2_fma(cc[3][1], A3d, bp1);
            }
            if (it < KC / BK - 1) {
                int nxt = cur ^ 1;
                As[nxt][loadK4 + 0][loadRow] = a.x;
                As[nxt][loadK4 + 1][loadRow] = a.y;
                As[nxt][loadK4 + 2][loadRow] = a.z;
                As[nxt][loadK4 + 3][loadRow] = a.w;
                Bs[nxt][loadK4 + 0][loadRow] = b4.x;
                Bs[nxt][loadK4 + 1][loadRow] = b4.y;
                Bs[nxt][loadK4 + 2][loadRow] = b4.z;
                Bs[nxt][loadK4 + 3][loadRow] = b4.w;
                __syncthreads();
            }
        }

        float* og = g_Gk[kz];
#pragma unroll
        for (int i = 0; i < 4; i++) {
            unsigned lo0, hi0, lo1, hi1;
            asm("mov.b64 {%0, %1}, %2;" : "=r"(lo0), "=r"(hi0) : "l"(cc[i][0]));
            asm("mov.b64 {%0, %1}, %2;" : "=r"(lo1), "=r"(hi1) : "l"(cc[i][1]));
            float4 v = make_float4(__uint_as_float(lo0), __uint_as_float(hi0),
                                   __uint_as_float(lo1), __uint_as_float(hi1));
            int row = bm * BM + ty4 + i;
            *(float4*)(og + (size_t)row * ROWS + bn * BN + tx4) = v;
        }
    }

    // ================== grid barrier over all GRID_ blocks ==================
    __syncthreads();
    if (tid == 0) {
        __threadfence();
        atomicAdd(&g_bar, 1);
        while (ld_cg(&g_bar) < GRID_) { __nanosleep(32); }
        __threadfence();
    }
    __syncthreads();

    // ================== loss phase (blocks 0-319, one query each) ==========
    if (bid < ROWS) {
        int q = bid;
        int labq = g_lab[q];
        float den = 0.f, num = 0.f;
        for (int n = tid; n < ROWS; n += 256) {
            float g = 0.f;
#pragma unroll
            for (int s = 0; s < SPLITK; s++) g += g_Gk[s][q * ROWS + n];
            float e = __expf(g * 0.0625f);          // TAU = 16
            e = g_val[n] ? e : 0.f;
            den += e;
            if (g_lab[n] == labq) num += e;
        }
#pragma unroll
        for (int o = 16; o; o >>= 1) {
            den += __shfl_down_sync(0xffffffffu, den, o);
            num += __shfl_down_sync(0xffffffffu, num, o);
        }
        if (lane == 0) { red[warp] = den; red[8 + warp] = num; }
        __syncthreads();
        if (tid == 0) {
            float d = 0.f, nm = 0.f;
#pragma unroll
            for (int w = 0; w < 8; w++) { d += red[w]; nm += red[8 + w]; }
            g_per[q] = g_val[q] ? -__logf(nm / d) : 0.f;
        }
    }

    // ================== completion counter over ALL blocks =================
    __syncthreads();
    if (tid == 0) {
        __threadfence();
        int o = atomicAdd(&g_cnt, 1);
        s_last = (o == GRID_ - 1);     // globally last -> all g_per visible
    }
    __syncthreads();

    if (s_last) {
        __threadfence();
        if (tid < B_) {
            int b = tid;
            float s = 0.f; int c = 0;
            for (int k = 0; k < KH; k++) { int r = b * KH + k; s += g_per[r]; c += g_val[r]; }
            for (int k = 0; k < KL; k++) { int r = HROWS + b * KL + k; s += g_per[r]; c += g_val[r]; }
            s_c[b] = s / (float)c;
            float se = __expf(ori[b * 2 + 0]) + __expf(ori[b * 2 + 1]);
            s_ce[b] = -__logf(__expf(t_logit[0]) / se);
        }
        __syncthreads();
        if (tid == 0) {
            float contr = 0.f, ce = 0.f;
#pragma unroll
            for (int b = 0; b < B_; b++) { contr += s_c[b]; ce += s_ce[b]; }
            contr /= (float)B_;
            ce /= (float)B_;

            unsigned mx = 0u;
            float sum = 0.f;
#pragma unroll
            for (int i = 0; i < B_; i++) { mx = max(mx, g_pmax[i]); sum += g_psum[i]; }
            float gmax = __uint_as_float(mx);
            float meanv = sum / (float)(B_ * N_);
            float Dm = meanv / gmax;
            float l2 = 0.0001f * (1.f - Dm) * (1.f - Dm) * l2w[0];

            out[0] = contr + ce + l2;
            // everyone has passed g_bar and g_seldone -> safe to reset:
            g_seldone = 0;
            g_bar = 0;
            g_cnt = 0;
            __threadfence();
        }
    }
}

// ---------------- launch ----------------
extern "C" void kernel_launch(void* const* d_in, const int* in_sizes, int n_in,
                              void* d_out, int out_size) {
    const float* fea     = (const float*)d_in[0];
    const float* score   = (const float*)d_in[1];
    const int*   label   = (const int*)d_in[2];
    const float* t_logit = (const float*)d_in[3];
    const float* ori     = (const float*)d_in[4];
    const float* l2w     = (const float*)d_in[5];
    float* out = (float*)d_out;

    k_all<<<GRID_, 256>>>(fea, score, label, t_logit, ori, l2w, out);
}